// round 5
// baseline (speedup 1.0000x reference)
#include <cuda_runtime.h>

#define NN 65536
#define NE 1048576
#define DD 64
#define NL 12
#define NM 2

// ---- device scratch (static allocation only, per harness rules) ----
__device__ float g_buf[NN * DD];      // ping buffer: conv output / next-layer input
__device__ float g_hw[NN * DD];       // hw = act(h) @ W
__device__ float g_dinv[NN];
__device__ int   g_deg[NN];
__device__ int   g_rowstart[NN + 1];
__device__ int   g_cursor[NN];
__device__ int2  g_csr[NE];           // {src, bitcast(dinv[src])}

// ---------------- CSR build ----------------
__global__ void k_zero_deg() {
    int i = blockIdx.x * blockDim.x + threadIdx.x;
    if (i < NN) g_deg[i] = 0;
}

__global__ void k_count(const int* __restrict__ dst) {
    int e = blockIdx.x * blockDim.x + threadIdx.x;
    if (e < NE) atomicAdd(&g_deg[dst[e] & (NN - 1)], 1);
}

__global__ void k_dinv() {
    int i = blockIdx.x * blockDim.x + threadIdx.x;
    if (i < NN) g_dinv[i] = rsqrtf((float)g_deg[i] + 1.0f);
}

// single-block exclusive scan of g_deg -> g_rowstart (+ cursor copy)
__global__ void k_scan() {
    __shared__ int part[1024];
    int t = threadIdx.x;
    int base = t * 64;
    int s = 0;
    for (int k = 0; k < 64; k++) s += g_deg[base + k];
    part[t] = s;
    __syncthreads();
    for (int off = 1; off < 1024; off <<= 1) {
        int v = (t >= off) ? part[t - off] : 0;
        __syncthreads();
        part[t] += v;
        __syncthreads();
    }
    int off = part[t] - s;  // exclusive base for this thread's chunk
    for (int k = 0; k < 64; k++) {
        g_rowstart[base + k] = off;
        g_cursor[base + k] = off;
        off += g_deg[base + k];
    }
    if (t == 1023) g_rowstart[NN] = off;
}

__global__ void k_fill(const int* __restrict__ src,
                       const int* __restrict__ dst) {
    int e = blockIdx.x * blockDim.x + threadIdx.x;
    if (e < NE) {
        int s = src[e] & (NN - 1);
        int d = dst[e] & (NN - 1);
        int pos = atomicAdd(&g_cursor[d], 1);
        g_csr[pos] = make_int2(s, __float_as_int(g_dinv[s]));
    }
}

// ---------------- GEMM: hw = act(A) @ W  (A: [NN,64], W: [64,64]) ----------------
// 256 threads, 64-row tile per block, 4x4 micro-tile per thread. ReLU fused on A load.
__global__ __launch_bounds__(256) void k_gemm(const float* __restrict__ A,
                                              const float* __restrict__ W,
                                              float* __restrict__ out,
                                              int relu) {
    __shared__ float As[64 * 64];
    __shared__ float Ws[64 * 64];
    int tid = threadIdx.x;

    const float4* A4 = (const float4*)(A + (size_t)blockIdx.x * 64 * DD);
    const float4* W4 = (const float4*)W;
    float4* As4 = (float4*)As;
    float4* Ws4 = (float4*)Ws;
#pragma unroll
    for (int k = 0; k < 4; k++) {
        float4 a = A4[tid + k * 256];
        if (relu) {
            a.x = fmaxf(a.x, 0.f); a.y = fmaxf(a.y, 0.f);
            a.z = fmaxf(a.z, 0.f); a.w = fmaxf(a.w, 0.f);
        }
        As4[tid + k * 256] = a;
        Ws4[tid + k * 256] = W4[tid + k * 256];
    }
    __syncthreads();

    int tx = tid & 15;   // col group
    int ty = tid >> 4;   // row group
    float acc[4][4];
#pragma unroll
    for (int m = 0; m < 4; m++)
#pragma unroll
        for (int n = 0; n < 4; n++) acc[m][n] = 0.f;

#pragma unroll
    for (int k = 0; k < 64; k++) {
        float4 w = *(const float4*)&Ws[k * 64 + tx * 4];
        float a0 = As[(ty * 4 + 0) * 64 + k];
        float a1 = As[(ty * 4 + 1) * 64 + k];
        float a2 = As[(ty * 4 + 2) * 64 + k];
        float a3 = As[(ty * 4 + 3) * 64 + k];
        acc[0][0] += a0 * w.x; acc[0][1] += a0 * w.y; acc[0][2] += a0 * w.z; acc[0][3] += a0 * w.w;
        acc[1][0] += a1 * w.x; acc[1][1] += a1 * w.y; acc[1][2] += a1 * w.z; acc[1][3] += a1 * w.w;
        acc[2][0] += a2 * w.x; acc[2][1] += a2 * w.y; acc[2][2] += a2 * w.z; acc[2][3] += a2 * w.w;
        acc[3][0] += a3 * w.x; acc[3][1] += a3 * w.y; acc[3][2] += a3 * w.z; acc[3][3] += a3 * w.w;
    }

    float4* O4 = (float4*)(out + (size_t)blockIdx.x * 64 * DD);
#pragma unroll
    for (int m = 0; m < 4; m++) {
        float4 r = make_float4(acc[m][0], acc[m][1], acc[m][2], acc[m][3]);
        O4[(ty * 4 + m) * 16 + tx] = r;
    }
}

// ---------------- AGG: out[n] = dinv[n]*sum_e dinv[src]*hw[src] + dinv[n]^2*hw[n] + b ----------------
// 16 threads per node, float4 lanes. Pure gather, no atomics.
__global__ __launch_bounds__(128) void k_agg(const float* __restrict__ hw,
                                             const float* __restrict__ b,
                                             float* __restrict__ out) {
    int t = threadIdx.x & 15;
    int nl = threadIdx.x >> 4;
    int n = blockIdx.x * 8 + nl;

    int beg = g_rowstart[n];
    int end = g_rowstart[n + 1];

    const float4* hw4 = (const float4*)hw;
    float4 acc = make_float4(0.f, 0.f, 0.f, 0.f);

    int e = beg;
    // 2-edge unrolled main loop for load-level parallelism
    for (; e + 1 < end; e += 2) {
        int2 sw0 = g_csr[e];
        int2 sw1 = g_csr[e + 1];
        float4 v0 = hw4[(size_t)sw0.x * 16 + t];
        float4 v1 = hw4[(size_t)sw1.x * 16 + t];
        float w0 = __int_as_float(sw0.y);
        float w1 = __int_as_float(sw1.y);
        acc.x += w0 * v0.x; acc.y += w0 * v0.y; acc.z += w0 * v0.z; acc.w += w0 * v0.w;
        acc.x += w1 * v1.x; acc.y += w1 * v1.y; acc.z += w1 * v1.z; acc.w += w1 * v1.w;
    }
    if (e < end) {
        int2 sw = g_csr[e];
        float w = __int_as_float(sw.y);
        float4 v = hw4[(size_t)sw.x * 16 + t];
        acc.x += w * v.x; acc.y += w * v.y; acc.z += w * v.z; acc.w += w * v.w;
    }

    float di = g_dinv[n];
    float d2 = di * di;
    float4 self = hw4[(size_t)n * 16 + t];
    float4 bb = ((const float4*)b)[t];
    float4 r;
    r.x = di * acc.x + d2 * self.x + bb.x;
    r.y = di * acc.y + d2 * self.y + bb.y;
    r.z = di * acc.z + d2 * self.z + bb.z;
    r.w = di * acc.w + d2 * self.w + bb.w;
    ((float4*)out)[(size_t)n * 16 + t] = r;
}

// ---------------- launcher ----------------
extern "C" void kernel_launch(void* const* d_in, const int* in_sizes, int n_in,
                              void* d_out, int out_size) {
    const float* x  = (const float*)d_in[0];
    const int*   ei = (const int*)d_in[1];   // int32: JAX demotes int64 with x64 disabled
    const float* W  = (const float*)d_in[2];
    const float* b  = (const float*)d_in[3];
    float*       out = (float*)d_out;

    float *pbuf, *phw;
    cudaGetSymbolAddress((void**)&pbuf, g_buf);
    cudaGetSymbolAddress((void**)&phw, g_hw);

    for (int i = 0; i < NM; i++) {
        const int* src = ei + (size_t)i * 2 * NE;
        const int* dst = src + NE;

        k_zero_deg<<<NN / 256, 256>>>();
        k_count<<<NE / 256, 256>>>(dst);
        k_dinv<<<NN / 256, 256>>>();
        k_scan<<<1, 1024>>>();
        k_fill<<<NE / 256, 256>>>(src, dst);

        const float* hin = x + (size_t)i * NN * DD;
        for (int j = 0; j < NL; j++) {
            const float* Wj = W + ((size_t)i * NL + j) * DD * DD;
            const float* bj = b + ((size_t)i * NL + j) * DD;
            const float* in = (j == 0) ? hin : (const float*)pbuf;
            float* outp = (j == NL - 1) ? (out + (size_t)i * NN * DD) : pbuf;

            k_gemm<<<NN / 64, 256>>>(in, Wj, phw, (j == 0) ? 0 : 1);
            k_agg<<<NN / 8, 128>>>(phw, bj, outp);
        }
    }
}

// round 6
// speedup vs baseline: 1.2985x; 1.2985x over previous
#include <cuda_runtime.h>

#define NN 65536
#define NE 1048576
#define DD 64
#define NL 12
#define NM 2
#define NB_G 1024   // gemm blocks per member-layer (64 rows each)
#define NB_A 4096   // agg blocks per member-layer (16 nodes each, 256 thr)

// ---- device scratch (static allocation only) ----
__device__ float g_buf[NM][NN * DD];
__device__ float g_hw[NM][NN * DD];
__device__ float g_dinv[NM][NN];
__device__ int   g_deg[NM][NN];
__device__ int   g_rowstart[NM][NN + 1];
__device__ int   g_cursor[NM][NN];
__device__ int2  g_csr[NM][NE];          // {src, bitcast(dinv[src])}
__device__ int   g_bsum[NM * 256];
__device__ int   g_boff[NM * 256];

// ---------------- CSR build ----------------
__global__ void k_zero_deg() {
    int i = blockIdx.x * blockDim.x + threadIdx.x;   // [0, 2*NN)
    ((int*)g_deg)[i] = 0;
}

__global__ void k_count(const int* __restrict__ ei) {
    int gi = blockIdx.x * blockDim.x + threadIdx.x;  // [0, 2*NE)
    int m = gi >> 20;                                // NE = 2^20
    int e = gi & (NE - 1);
    int d = ei[(size_t)m * 2 * NE + NE + e] & (NN - 1);
    atomicAdd(&g_deg[m][d], 1);
}

// per-256-chunk sums + dinv.  grid = 512, block = 256
__global__ void k_blocksum() {
    __shared__ int red[256];
    int m = blockIdx.x >> 8;
    int cb = blockIdx.x & 255;
    int node = cb * 256 + threadIdx.x;
    int d = g_deg[m][node];
    g_dinv[m][node] = rsqrtf((float)d + 1.0f);
    red[threadIdx.x] = d;
    __syncthreads();
    for (int off = 128; off > 0; off >>= 1) {
        if (threadIdx.x < off) red[threadIdx.x] += red[threadIdx.x + off];
        __syncthreads();
    }
    if (threadIdx.x == 0) g_bsum[m * 256 + cb] = red[0];
}

// scan of chunk sums. grid = 2 (one per member), block = 256
__global__ void k_scanb() {
    __shared__ int s[256];
    int t = threadIdx.x;
    int v = g_bsum[blockIdx.x * 256 + t];
    s[t] = v;
    __syncthreads();
    for (int off = 1; off < 256; off <<= 1) {
        int u = (t >= off) ? s[t - off] : 0;
        __syncthreads();
        s[t] += u;
        __syncthreads();
    }
    g_boff[blockIdx.x * 256 + t] = s[t] - v;   // exclusive
}

// per-chunk exclusive scan + base offset -> rowstart/cursor. grid = 512, block = 256
__global__ void k_rowstart() {
    __shared__ int s[256];
    int m = blockIdx.x >> 8;
    int cb = blockIdx.x & 255;
    int t = threadIdx.x;
    int node = cb * 256 + t;
    int d = g_deg[m][node];
    s[t] = d;
    __syncthreads();
    for (int off = 1; off < 256; off <<= 1) {
        int u = (t >= off) ? s[t - off] : 0;
        __syncthreads();
        s[t] += u;
        __syncthreads();
    }
    int rs = g_boff[m * 256 + cb] + s[t] - d;  // exclusive within member
    g_rowstart[m][node] = rs;
    g_cursor[m][node] = rs;
    if (node == NN - 1) g_rowstart[m][NN] = rs + d;
}

__global__ void k_fill(const int* __restrict__ ei) {
    int gi = blockIdx.x * blockDim.x + threadIdx.x;  // [0, 2*NE)
    int m = gi >> 20;
    int e = gi & (NE - 1);
    int s = ei[(size_t)m * 2 * NE + e] & (NN - 1);
    int d = ei[(size_t)m * 2 * NE + NE + e] & (NN - 1);
    int pos = atomicAdd(&g_cursor[m][d], 1);
    g_csr[m][pos] = make_int2(s, __float_as_int(g_dinv[m][s]));
}

// ---------------- fused pipeline kernel ----------------
// gemm part: hw = act(A) @ W for one member/layer (ng blocks of 64 rows)
// agg  part: out[n] = dinv[n]*sum_e dinv[src]*hw[src] + dinv[n]^2*hw[n] + b
// block-id interleave 1:4 when both present (ng=1024, na=4096)
__global__ __launch_bounds__(256) void k_fused(
    const float* __restrict__ gA, const float* __restrict__ gW,
    float* __restrict__ gO, int relu, int ng,
    const float* __restrict__ ahw, const float* __restrict__ abv,
    float* __restrict__ aout, int am, int na)
{
    int gb = -1, abk = -1;
    if (ng && na) {
        int q = blockIdx.x / 5, r = blockIdx.x % 5;
        if (r == 0) gb = q; else abk = q * 4 + r - 1;
    } else if (ng) {
        gb = blockIdx.x;
    } else {
        abk = blockIdx.x;
    }

    if (gb >= 0) {
        // ---- GEMM path ----
        __shared__ float As[64 * 64];
        __shared__ float Ws[64 * 64];
        int tid = threadIdx.x;
        const float4* A4 = (const float4*)(gA + (size_t)gb * 64 * DD);
        const float4* W4 = (const float4*)gW;
        float4* As4 = (float4*)As;
        float4* Ws4 = (float4*)Ws;
#pragma unroll
        for (int k = 0; k < 4; k++) {
            float4 a = A4[tid + k * 256];
            if (relu) {
                a.x = fmaxf(a.x, 0.f); a.y = fmaxf(a.y, 0.f);
                a.z = fmaxf(a.z, 0.f); a.w = fmaxf(a.w, 0.f);
            }
            As4[tid + k * 256] = a;
            Ws4[tid + k * 256] = W4[tid + k * 256];
        }
        __syncthreads();

        int tx = tid & 15;
        int ty = tid >> 4;
        float acc[4][4];
#pragma unroll
        for (int m = 0; m < 4; m++)
#pragma unroll
            for (int n = 0; n < 4; n++) acc[m][n] = 0.f;

#pragma unroll
        for (int k = 0; k < 64; k++) {
            float4 w = *(const float4*)&Ws[k * 64 + tx * 4];
            float a0 = As[(ty * 4 + 0) * 64 + k];
            float a1 = As[(ty * 4 + 1) * 64 + k];
            float a2 = As[(ty * 4 + 2) * 64 + k];
            float a3 = As[(ty * 4 + 3) * 64 + k];
            acc[0][0] += a0 * w.x; acc[0][1] += a0 * w.y; acc[0][2] += a0 * w.z; acc[0][3] += a0 * w.w;
            acc[1][0] += a1 * w.x; acc[1][1] += a1 * w.y; acc[1][2] += a1 * w.z; acc[1][3] += a1 * w.w;
            acc[2][0] += a2 * w.x; acc[2][1] += a2 * w.y; acc[2][2] += a2 * w.z; acc[2][3] += a2 * w.w;
            acc[3][0] += a3 * w.x; acc[3][1] += a3 * w.y; acc[3][2] += a3 * w.z; acc[3][3] += a3 * w.w;
        }

        float4* O4 = (float4*)(gO + (size_t)gb * 64 * DD);
#pragma unroll
        for (int m = 0; m < 4; m++)
            O4[(ty * 4 + m) * 16 + tx] = make_float4(acc[m][0], acc[m][1], acc[m][2], acc[m][3]);
    } else {
        // ---- AGG path ----
        int t = threadIdx.x & 15;
        int nl = threadIdx.x >> 4;           // 0..15
        int n = abk * 16 + nl;

        int beg = g_rowstart[am][n];
        int end = g_rowstart[am][n + 1];

        const float4* hw4 = (const float4*)ahw;
        const int2* csr = g_csr[am];
        float4 acc = make_float4(0.f, 0.f, 0.f, 0.f);

        int e = beg;
        for (; e + 1 < end; e += 2) {
            int2 sw0 = csr[e];
            int2 sw1 = csr[e + 1];
            float4 v0 = hw4[(size_t)sw0.x * 16 + t];
            float4 v1 = hw4[(size_t)sw1.x * 16 + t];
            float w0 = __int_as_float(sw0.y);
            float w1 = __int_as_float(sw1.y);
            acc.x += w0 * v0.x; acc.y += w0 * v0.y; acc.z += w0 * v0.z; acc.w += w0 * v0.w;
            acc.x += w1 * v1.x; acc.y += w1 * v1.y; acc.z += w1 * v1.z; acc.w += w1 * v1.w;
        }
        if (e < end) {
            int2 sw = csr[e];
            float w = __int_as_float(sw.y);
            float4 v = hw4[(size_t)sw.x * 16 + t];
            acc.x += w * v.x; acc.y += w * v.y; acc.z += w * v.z; acc.w += w * v.w;
        }

        float di = g_dinv[am][n];
        float d2 = di * di;
        float4 self = hw4[(size_t)n * 16 + t];
        float4 bb = ((const float4*)abv)[t];
        float4 r;
        r.x = di * acc.x + d2 * self.x + bb.x;
        r.y = di * acc.y + d2 * self.y + bb.y;
        r.z = di * acc.z + d2 * self.z + bb.z;
        r.w = di * acc.w + d2 * self.w + bb.w;
        ((float4*)aout)[(size_t)n * 16 + t] = r;
    }
}

// ---------------- launcher ----------------
extern "C" void kernel_launch(void* const* d_in, const int* in_sizes, int n_in,
                              void* d_out, int out_size) {
    const float* x  = (const float*)d_in[0];
    const int*   ei = (const int*)d_in[1];   // int32 (JAX demotes int64)
    const float* W  = (const float*)d_in[2];
    const float* b  = (const float*)d_in[3];
    float*       out = (float*)d_out;

    float (*pbuf)[NN * DD];
    float (*phw)[NN * DD];
    cudaGetSymbolAddress((void**)&pbuf, g_buf);
    cudaGetSymbolAddress((void**)&phw, g_hw);

    // ---- CSR build for both members ----
    k_zero_deg<<<2 * NN / 256, 256>>>();
    k_count<<<2 * NE / 256, 256>>>(ei);
    k_blocksum<<<512, 256>>>();
    k_scanb<<<2, 256>>>();
    k_rowstart<<<512, 256>>>();
    k_fill<<<2 * NE / 256, 256>>>(ei);

    // per-member helpers
    const float* xin[NM]   = { x, x + (size_t)NN * DD };
    float*       outp[NM]  = { out, out + (size_t)NN * DD };
    auto Wp = [&](int m, int j) { return W + ((size_t)m * NL + j) * DD * DD; };
    auto bp = [&](int m, int j) { return b + ((size_t)m * NL + j) * DD; };

    // ---- 2-member software pipeline, 25 launches ----
    // L0          : G(m0,0)
    // L(2k+1)     : A(m0,k)  || G(m1,k)      k=0..11
    // L(2k), k>=1 : G(m0,k)  || A(m1,k-1)    k=1..11
    // L24         : A(m1,11)
    k_fused<<<NB_G, 256>>>(xin[0], Wp(0, 0), phw[0], 0, NB_G,
                           nullptr, nullptr, nullptr, 0, 0);
    for (int k = 1; k <= 23; k++) {
        if (k & 1) {
            int j = (k - 1) / 2;
            const float* gin = (j == 0) ? xin[1] : pbuf[1];
            float* aout = (j == NL - 1) ? outp[0] : pbuf[0];
            k_fused<<<NB_G + NB_A, 256>>>(gin, Wp(1, j), phw[1], (j != 0), NB_G,
                                          phw[0], bp(0, j), aout, 0, NB_A);
        } else {
            int j = k / 2;
            float* aout = pbuf[1];                 // j-1 <= 10, never final
            k_fused<<<NB_G + NB_A, 256>>>(pbuf[0], Wp(0, j), phw[0], 1, NB_G,
                                          phw[1], bp(1, j - 1), aout, 1, NB_A);
        }
    }
    k_fused<<<NB_A, 256>>>(nullptr, nullptr, nullptr, 0, 0,
                           phw[1], bp(1, NL - 1), outp[1], 1, NB_A);
}

// round 7
// speedup vs baseline: 1.4062x; 1.0829x over previous
#include <cuda_runtime.h>

#define NN 65536
#define NE 1048576
#define DD 64
#define NL 12
#define NM 2

// ---- device scratch (static allocation only) ----
__device__ float g_bufA[NM][NN * DD];
__device__ float g_bufB[NM][NN * DD];
__device__ float g_dinv[NM][NN];
__device__ int   g_deg[NM][NN];
__device__ int   g_rowstart[NM][NN + 1];
__device__ int   g_cursor[NM][NN];
__device__ int2  g_csr[NM][NE];          // {src, bitcast(dinv[src])}
__device__ int   g_bsum[NM * 256];
__device__ int   g_boff[NM * 256];

// ---------------- CSR build ----------------
__global__ void k_zero_deg() {
    int i = blockIdx.x * blockDim.x + threadIdx.x;   // [0, 2*NN)
    ((int*)g_deg)[i] = 0;
}

__global__ void k_count(const int* __restrict__ ei) {
    int gi = blockIdx.x * blockDim.x + threadIdx.x;  // [0, 2*NE)
    int m = gi >> 20;                                // NE = 2^20
    int e = gi & (NE - 1);
    int d = ei[(size_t)m * 2 * NE + NE + e] & (NN - 1);
    atomicAdd(&g_deg[m][d], 1);
}

// per-256-chunk sums + dinv.  grid = 512, block = 256
__global__ void k_blocksum() {
    __shared__ int red[256];
    int m = blockIdx.x >> 8;
    int cb = blockIdx.x & 255;
    int node = cb * 256 + threadIdx.x;
    int d = g_deg[m][node];
    g_dinv[m][node] = rsqrtf((float)d + 1.0f);
    red[threadIdx.x] = d;
    __syncthreads();
    for (int off = 128; off > 0; off >>= 1) {
        if (threadIdx.x < off) red[threadIdx.x] += red[threadIdx.x + off];
        __syncthreads();
    }
    if (threadIdx.x == 0) g_bsum[m * 256 + cb] = red[0];
}

// scan of chunk sums. grid = 2 (one per member), block = 256
__global__ void k_scanb() {
    __shared__ int s[256];
    int t = threadIdx.x;
    int v = g_bsum[blockIdx.x * 256 + t];
    s[t] = v;
    __syncthreads();
    for (int off = 1; off < 256; off <<= 1) {
        int u = (t >= off) ? s[t - off] : 0;
        __syncthreads();
        s[t] += u;
        __syncthreads();
    }
    g_boff[blockIdx.x * 256 + t] = s[t] - v;   // exclusive
}

// per-chunk exclusive scan + base offset -> rowstart/cursor. grid = 512, block = 256
__global__ void k_rowstart() {
    __shared__ int s[256];
    int m = blockIdx.x >> 8;
    int cb = blockIdx.x & 255;
    int t = threadIdx.x;
    int node = cb * 256 + t;
    int d = g_deg[m][node];
    s[t] = d;
    __syncthreads();
    for (int off = 1; off < 256; off <<= 1) {
        int u = (t >= off) ? s[t - off] : 0;
        __syncthreads();
        s[t] += u;
        __syncthreads();
    }
    int rs = g_boff[m * 256 + cb] + s[t] - d;  // exclusive within member
    g_rowstart[m][node] = rs;
    g_cursor[m][node] = rs;
    if (node == NN - 1) g_rowstart[m][NN] = rs + d;
}

__global__ void k_fill(const int* __restrict__ ei) {
    int gi = blockIdx.x * blockDim.x + threadIdx.x;  // [0, 2*NE)
    int m = gi >> 20;
    int e = gi & (NE - 1);
    int s = ei[(size_t)m * 2 * NE + e] & (NN - 1);
    int d = ei[(size_t)m * 2 * NE + NE + e] & (NN - 1);
    int pos = atomicAdd(&g_cursor[m][d], 1);
    g_csr[m][pos] = make_int2(s, __float_as_int(g_dinv[m][s]));
}

// ---------------- fused layer: out = maybe_relu( (A_norm @ h) @ W + b ) ----------------
// One block = 64 output nodes (one member). Phase 1: gather+aggregate h rows into
// smem As. Phase 2: 64x64 GEMM with W + bias (+ReLU). 2048 blocks = both members.
__global__ __launch_bounds__(256) void k_layer(
    const float* __restrict__ hin,   // [NM*NN*DD] (or x)
    float* __restrict__ hout,        // [NM*NN*DD] (or d_out)
    const float* __restrict__ Wbase, // [NM][NL][DD*DD]
    const float* __restrict__ bbase, // [NM][NL][DD]
    int j, int relu)
{
    __shared__ float As[64 * 64];
    __shared__ float Ws[64 * 64];

    int tid = threadIdx.x;
    int m = blockIdx.x >> 10;
    int tile = blockIdx.x & 1023;

    const float* hin_m = hin + (size_t)m * NN * DD;
    float* hout_m = hout + (size_t)m * NN * DD;
    const float* Wj = Wbase + ((size_t)m * NL + j) * DD * DD;
    const float* bj = bbase + ((size_t)m * NL + j) * DD;

    // load W tile (overlaps with gather issue; consumed after the barrier)
    {
        const float4* W4 = (const float4*)Wj;
        float4* Ws4 = (float4*)Ws;
#pragma unroll
        for (int k = 0; k < 4; k++) Ws4[tid + k * 256] = W4[tid + k * 256];
    }

    // ---- Phase 1: aggregate 64 rows of h into As ----
    {
        int t = tid & 15;        // feature lane (float4)
        int grp = tid >> 4;      // 16 node groups
        const float4* h4 = (const float4*)hin_m;
        const int2* csr = g_csr[m];

#pragma unroll
        for (int g = 0; g < 4; g++) {
            int nl = g * 16 + grp;
            int n = tile * 64 + nl;
            int beg = g_rowstart[m][n];
            int end = g_rowstart[m][n + 1];

            float4 acc = make_float4(0.f, 0.f, 0.f, 0.f);
            int e = beg;
            for (; e + 3 < end; e += 4) {
                int2 s0 = csr[e];
                int2 s1 = csr[e + 1];
                int2 s2 = csr[e + 2];
                int2 s3 = csr[e + 3];
                float4 v0 = h4[(size_t)s0.x * 16 + t];
                float4 v1 = h4[(size_t)s1.x * 16 + t];
                float4 v2 = h4[(size_t)s2.x * 16 + t];
                float4 v3 = h4[(size_t)s3.x * 16 + t];
                float w0 = __int_as_float(s0.y);
                float w1 = __int_as_float(s1.y);
                float w2 = __int_as_float(s2.y);
                float w3 = __int_as_float(s3.y);
                acc.x += w0 * v0.x; acc.y += w0 * v0.y; acc.z += w0 * v0.z; acc.w += w0 * v0.w;
                acc.x += w1 * v1.x; acc.y += w1 * v1.y; acc.z += w1 * v1.z; acc.w += w1 * v1.w;
                acc.x += w2 * v2.x; acc.y += w2 * v2.y; acc.z += w2 * v2.z; acc.w += w2 * v2.w;
                acc.x += w3 * v3.x; acc.y += w3 * v3.y; acc.z += w3 * v3.z; acc.w += w3 * v3.w;
            }
            for (; e < end; e++) {
                int2 sw = csr[e];
                float w = __int_as_float(sw.y);
                float4 v = h4[(size_t)sw.x * 16 + t];
                acc.x += w * v.x; acc.y += w * v.y; acc.z += w * v.z; acc.w += w * v.w;
            }

            float di = g_dinv[m][n];
            float d2 = di * di;
            float4 self = h4[(size_t)n * 16 + t];
            float4 r;
            r.x = di * acc.x + d2 * self.x;
            r.y = di * acc.y + d2 * self.y;
            r.z = di * acc.z + d2 * self.z;
            r.w = di * acc.w + d2 * self.w;
            *(float4*)&As[nl * 64 + t * 4] = r;
        }
    }
    __syncthreads();

    // ---- Phase 2: [64x64] @ W + b (+ReLU) ----
    {
        int tx = tid & 15;
        int ty = tid >> 4;
        float acc[4][4];
#pragma unroll
        for (int mm = 0; mm < 4; mm++)
#pragma unroll
            for (int nn = 0; nn < 4; nn++) acc[mm][nn] = 0.f;

#pragma unroll
        for (int k = 0; k < 64; k++) {
            float4 w = *(const float4*)&Ws[k * 64 + tx * 4];
            float a0 = As[(ty * 4 + 0) * 64 + k];
            float a1 = As[(ty * 4 + 1) * 64 + k];
            float a2 = As[(ty * 4 + 2) * 64 + k];
            float a3 = As[(ty * 4 + 3) * 64 + k];
            acc[0][0] += a0 * w.x; acc[0][1] += a0 * w.y; acc[0][2] += a0 * w.z; acc[0][3] += a0 * w.w;
            acc[1][0] += a1 * w.x; acc[1][1] += a1 * w.y; acc[1][2] += a1 * w.z; acc[1][3] += a1 * w.w;
            acc[2][0] += a2 * w.x; acc[2][1] += a2 * w.y; acc[2][2] += a2 * w.z; acc[2][3] += a2 * w.w;
            acc[3][0] += a3 * w.x; acc[3][1] += a3 * w.y; acc[3][2] += a3 * w.z; acc[3][3] += a3 * w.w;
        }

        float4 bb = ((const float4*)bj)[tx];
        float4* O4 = (float4*)hout_m;
#pragma unroll
        for (int mm = 0; mm < 4; mm++) {
            float4 r;
            r.x = acc[mm][0] + bb.x;
            r.y = acc[mm][1] + bb.y;
            r.z = acc[mm][2] + bb.z;
            r.w = acc[mm][3] + bb.w;
            if (relu) {
                r.x = fmaxf(r.x, 0.f); r.y = fmaxf(r.y, 0.f);
                r.z = fmaxf(r.z, 0.f); r.w = fmaxf(r.w, 0.f);
            }
            O4[((size_t)tile * 64 + ty * 4 + mm) * 16 + tx] = r;
        }
    }
}

// ---------------- launcher ----------------
extern "C" void kernel_launch(void* const* d_in, const int* in_sizes, int n_in,
                              void* d_out, int out_size) {
    const float* x  = (const float*)d_in[0];
    const int*   ei = (const int*)d_in[1];   // int32 (JAX demotes int64)
    const float* W  = (const float*)d_in[2];
    const float* b  = (const float*)d_in[3];
    float*       out = (float*)d_out;

    float* bufA;
    float* bufB;
    cudaGetSymbolAddress((void**)&bufA, g_bufA);
    cudaGetSymbolAddress((void**)&bufB, g_bufB);

    // ---- CSR build for both members ----
    k_zero_deg<<<2 * NN / 256, 256>>>();
    k_count<<<2 * NE / 256, 256>>>(ei);
    k_blocksum<<<512, 256>>>();
    k_scanb<<<2, 256>>>();
    k_rowstart<<<512, 256>>>();
    k_fill<<<2 * NE / 256, 256>>>(ei);

    // ---- 12 fused layers, both members per launch ----
    const float* in = x;
    float* bufs[2] = { bufA, bufB };
    for (int j = 0; j < NL; j++) {
        float* outp = (j == NL - 1) ? out : bufs[j & 1];
        k_layer<<<2048, 256>>>(in, outp, W, b, j, (j != NL - 1));
        in = outp;
    }
}

// round 8
// speedup vs baseline: 1.5589x; 1.1086x over previous
#include <cuda_runtime.h>
#include <cuda_fp16.h>

#define NN 65536
#define NE 1048576
#define DD 64
#define NL 12
#define NM 2

// ---- device scratch (static allocation only) ----
__device__ __half g_hA[NM][NN * DD];     // fp16 ping
__device__ __half g_hB[NM][NN * DD];     // fp16 pong
__device__ float g_dinv[NM][NN];
__device__ int   g_deg[NM][NN];
__device__ int   g_rowstart[NM][NN + 1];
__device__ int   g_cursor[NM][NN];
__device__ int2  g_csr[NM][NE];          // {src, bitcast(dinv[src])}
__device__ int   g_bsum[NM * 256];
__device__ int   g_boff[NM * 256];

// ---------------- CSR build ----------------
__global__ void k_zero_deg() {
    int i = blockIdx.x * blockDim.x + threadIdx.x;   // [0, 2*NN)
    ((int*)g_deg)[i] = 0;
}

__global__ void k_count(const int* __restrict__ ei) {
    int gi = blockIdx.x * blockDim.x + threadIdx.x;  // [0, 2*NE)
    int m = gi >> 20;                                // NE = 2^20
    int e = gi & (NE - 1);
    int d = ei[(size_t)m * 2 * NE + NE + e] & (NN - 1);
    atomicAdd(&g_deg[m][d], 1);
}

// per-256-chunk sums + dinv.  grid = 512, block = 256
__global__ void k_blocksum() {
    __shared__ int red[256];
    int m = blockIdx.x >> 8;
    int cb = blockIdx.x & 255;
    int node = cb * 256 + threadIdx.x;
    int d = g_deg[m][node];
    g_dinv[m][node] = rsqrtf((float)d + 1.0f);
    red[threadIdx.x] = d;
    __syncthreads();
    for (int off = 128; off > 0; off >>= 1) {
        if (threadIdx.x < off) red[threadIdx.x] += red[threadIdx.x + off];
        __syncthreads();
    }
    if (threadIdx.x == 0) g_bsum[m * 256 + cb] = red[0];
}

// scan of chunk sums. grid = 2 (one per member), block = 256
__global__ void k_scanb() {
    __shared__ int s[256];
    int t = threadIdx.x;
    int v = g_bsum[blockIdx.x * 256 + t];
    s[t] = v;
    __syncthreads();
    for (int off = 1; off < 256; off <<= 1) {
        int u = (t >= off) ? s[t - off] : 0;
        __syncthreads();
        s[t] += u;
        __syncthreads();
    }
    g_boff[blockIdx.x * 256 + t] = s[t] - v;   // exclusive
}

// per-chunk exclusive scan + base offset. grid = 512, block = 256
__global__ void k_rowstart() {
    __shared__ int s[256];
    int m = blockIdx.x >> 8;
    int cb = blockIdx.x & 255;
    int t = threadIdx.x;
    int node = cb * 256 + t;
    int d = g_deg[m][node];
    s[t] = d;
    __syncthreads();
    for (int off = 1; off < 256; off <<= 1) {
        int u = (t >= off) ? s[t - off] : 0;
        __syncthreads();
        s[t] += u;
        __syncthreads();
    }
    int rs = g_boff[m * 256 + cb] + s[t] - d;
    g_rowstart[m][node] = rs;
    g_cursor[m][node] = rs;
    if (node == NN - 1) g_rowstart[m][NN] = rs + d;
}

__global__ void k_fill(const int* __restrict__ ei) {
    int gi = blockIdx.x * blockDim.x + threadIdx.x;  // [0, 2*NE)
    int m = gi >> 20;
    int e = gi & (NE - 1);
    int s = ei[(size_t)m * 2 * NE + e] & (NN - 1);
    int d = ei[(size_t)m * 2 * NE + NE + e] & (NN - 1);
    int pos = atomicAdd(&g_cursor[m][d], 1);
    g_csr[m][pos] = make_int2(s, __float_as_int(g_dinv[m][s]));
}

// ---------------- fused layer: out = maybe_relu( (A_norm @ h) @ W + b ) ----------------
// IN16/OUT16 select fp16 vs fp32 activation storage. Arithmetic is fp32 throughout.
template<bool IN16, bool OUT16>
__global__ __launch_bounds__(256) void k_layer(
    const void* __restrict__ hin,
    void* __restrict__ hout,
    const float* __restrict__ Wbase,
    const float* __restrict__ bbase,
    int j, int relu)
{
    __shared__ float As[64 * 64];
    __shared__ float Ws[64 * 64];

    int tid = threadIdx.x;
    int m = blockIdx.x >> 10;
    int tile = blockIdx.x & 1023;

    const float* Wj = Wbase + ((size_t)m * NL + j) * DD * DD;
    const float* bj = bbase + ((size_t)m * NL + j) * DD;

    // load W tile
    {
        const float4* W4 = (const float4*)Wj;
        float4* Ws4 = (float4*)Ws;
#pragma unroll
        for (int k = 0; k < 4; k++) Ws4[tid + k * 256] = W4[tid + k * 256];
    }

    // ---- Phase 1: aggregate 64 rows of h into As ----
    {
        int t = tid & 15;        // feature lane (4 features)
        int grp = tid >> 4;      // 16 node groups
        const int2* csr = g_csr[m];

        const float4* h4 = (const float4*)hin + (IN16 ? 0 : (size_t)m * NN * 16);
        const uint2*  h2 = (const uint2*)hin + (IN16 ? (size_t)m * NN * 16 : 0);

#pragma unroll
        for (int g = 0; g < 4; g++) {
            int nl = g * 16 + grp;
            int n = tile * 64 + nl;
            int beg = g_rowstart[m][n];
            int end = g_rowstart[m][n + 1];

            float4 acc = make_float4(0.f, 0.f, 0.f, 0.f);
            int e = beg;
            for (; e + 3 < end; e += 4) {
                int2 s0 = csr[e];
                int2 s1 = csr[e + 1];
                int2 s2 = csr[e + 2];
                int2 s3 = csr[e + 3];
                float4 v0, v1, v2, v3;
                if (IN16) {
                    uint2 r0 = h2[(size_t)s0.x * 16 + t];
                    uint2 r1 = h2[(size_t)s1.x * 16 + t];
                    uint2 r2 = h2[(size_t)s2.x * 16 + t];
                    uint2 r3 = h2[(size_t)s3.x * 16 + t];
                    float2 a, bq;
                    a = __half22float2(*(half2*)&r0.x); bq = __half22float2(*(half2*)&r0.y);
                    v0 = make_float4(a.x, a.y, bq.x, bq.y);
                    a = __half22float2(*(half2*)&r1.x); bq = __half22float2(*(half2*)&r1.y);
                    v1 = make_float4(a.x, a.y, bq.x, bq.y);
                    a = __half22float2(*(half2*)&r2.x); bq = __half22float2(*(half2*)&r2.y);
                    v2 = make_float4(a.x, a.y, bq.x, bq.y);
                    a = __half22float2(*(half2*)&r3.x); bq = __half22float2(*(half2*)&r3.y);
                    v3 = make_float4(a.x, a.y, bq.x, bq.y);
                } else {
                    v0 = h4[(size_t)s0.x * 16 + t];
                    v1 = h4[(size_t)s1.x * 16 + t];
                    v2 = h4[(size_t)s2.x * 16 + t];
                    v3 = h4[(size_t)s3.x * 16 + t];
                }
                float w0 = __int_as_float(s0.y);
                float w1 = __int_as_float(s1.y);
                float w2 = __int_as_float(s2.y);
                float w3 = __int_as_float(s3.y);
                acc.x += w0 * v0.x; acc.y += w0 * v0.y; acc.z += w0 * v0.z; acc.w += w0 * v0.w;
                acc.x += w1 * v1.x; acc.y += w1 * v1.y; acc.z += w1 * v1.z; acc.w += w1 * v1.w;
                acc.x += w2 * v2.x; acc.y += w2 * v2.y; acc.z += w2 * v2.z; acc.w += w2 * v2.w;
                acc.x += w3 * v3.x; acc.y += w3 * v3.y; acc.z += w3 * v3.z; acc.w += w3 * v3.w;
            }
            for (; e < end; e++) {
                int2 sw = csr[e];
                float w = __int_as_float(sw.y);
                float4 v;
                if (IN16) {
                    uint2 r0 = h2[(size_t)sw.x * 16 + t];
                    float2 a = __half22float2(*(half2*)&r0.x);
                    float2 bq = __half22float2(*(half2*)&r0.y);
                    v = make_float4(a.x, a.y, bq.x, bq.y);
                } else {
                    v = h4[(size_t)sw.x * 16 + t];
                }
                acc.x += w * v.x; acc.y += w * v.y; acc.z += w * v.z; acc.w += w * v.w;
            }

            float di = g_dinv[m][n];
            float d2 = di * di;
            float4 self;
            if (IN16) {
                uint2 r0 = h2[(size_t)n * 16 + t];
                float2 a = __half22float2(*(half2*)&r0.x);
                float2 bq = __half22float2(*(half2*)&r0.y);
                self = make_float4(a.x, a.y, bq.x, bq.y);
            } else {
                self = h4[(size_t)n * 16 + t];
            }
            float4 r;
            r.x = di * acc.x + d2 * self.x;
            r.y = di * acc.y + d2 * self.y;
            r.z = di * acc.z + d2 * self.z;
            r.w = di * acc.w + d2 * self.w;
            *(float4*)&As[nl * 64 + t * 4] = r;
        }
    }
    __syncthreads();

    // ---- Phase 2: [64x64] @ W + b (+ReLU) ----
    {
        int tx = tid & 15;
        int ty = tid >> 4;
        float acc[4][4];
#pragma unroll
        for (int mm = 0; mm < 4; mm++)
#pragma unroll
            for (int nn = 0; nn < 4; nn++) acc[mm][nn] = 0.f;

#pragma unroll
        for (int k = 0; k < 64; k++) {
            float4 w = *(const float4*)&Ws[k * 64 + tx * 4];
            float a0 = As[(ty * 4 + 0) * 64 + k];
            float a1 = As[(ty * 4 + 1) * 64 + k];
            float a2 = As[(ty * 4 + 2) * 64 + k];
            float a3 = As[(ty * 4 + 3) * 64 + k];
            acc[0][0] += a0 * w.x; acc[0][1] += a0 * w.y; acc[0][2] += a0 * w.z; acc[0][3] += a0 * w.w;
            acc[1][0] += a1 * w.x; acc[1][1] += a1 * w.y; acc[1][2] += a1 * w.z; acc[1][3] += a1 * w.w;
            acc[2][0] += a2 * w.x; acc[2][1] += a2 * w.y; acc[2][2] += a2 * w.z; acc[2][3] += a2 * w.w;
            acc[3][0] += a3 * w.x; acc[3][1] += a3 * w.y; acc[3][2] += a3 * w.z; acc[3][3] += a3 * w.w;
        }

        float4 bb = ((const float4*)bj)[tx];
#pragma unroll
        for (int mm = 0; mm < 4; mm++) {
            float4 r;
            r.x = acc[mm][0] + bb.x;
            r.y = acc[mm][1] + bb.y;
            r.z = acc[mm][2] + bb.z;
            r.w = acc[mm][3] + bb.w;
            if (relu) {
                r.x = fmaxf(r.x, 0.f); r.y = fmaxf(r.y, 0.f);
                r.z = fmaxf(r.z, 0.f); r.w = fmaxf(r.w, 0.f);
            }
            size_t row = (size_t)tile * 64 + ty * 4 + mm;
            if (OUT16) {
                half2 p0 = __floats2half2_rn(r.x, r.y);
                half2 p1 = __floats2half2_rn(r.z, r.w);
                uint2 o;
                o.x = *(unsigned int*)&p0;
                o.y = *(unsigned int*)&p1;
                ((uint2*)hout)[((size_t)m * NN + row) * 16 + tx] = o;
            } else {
                ((float4*)hout)[((size_t)m * NN + row) * 16 + tx] = r;
            }
        }
    }
}

// ---------------- launcher ----------------
extern "C" void kernel_launch(void* const* d_in, const int* in_sizes, int n_in,
                              void* d_out, int out_size) {
    const float* x  = (const float*)d_in[0];
    const int*   ei = (const int*)d_in[1];   // int32 (JAX demotes int64)
    const float* W  = (const float*)d_in[2];
    const float* b  = (const float*)d_in[3];
    float*       out = (float*)d_out;

    void* hA;
    void* hB;
    cudaGetSymbolAddress(&hA, g_hA);
    cudaGetSymbolAddress(&hB, g_hB);

    // ---- CSR build for both members ----
    k_zero_deg<<<2 * NN / 256, 256>>>();
    k_count<<<2 * NE / 256, 256>>>(ei);
    k_blocksum<<<512, 256>>>();
    k_scanb<<<2, 256>>>();
    k_rowstart<<<512, 256>>>();
    k_fill<<<2 * NE / 256, 256>>>(ei);

    // ---- 12 fused layers, both members per launch ----
    // layer 0: fp32 in (x), fp16 out; layers 1..10: fp16->fp16; layer 11: fp16->fp32 (d_out)
    void* bufs[2] = { hA, hB };
    k_layer<false, true><<<2048, 256>>>(x, bufs[0], W, b, 0, 1);
    const void* in = bufs[0];
    for (int j = 1; j <= 10; j++) {
        void* outp = bufs[j & 1];
        k_layer<true, true><<<2048, 256>>>(in, outp, W, b, j, 1);
        in = outp;
    }
    k_layer<true, false><<<2048, 256>>>(in, out, W, b, 11, 0);
}

// round 9
// speedup vs baseline: 1.6296x; 1.0454x over previous
#include <cuda_runtime.h>
#include <cuda_fp16.h>

#define NN 65536
#define NE 1048576
#define DD 64
#define NL 12
#define NM 2
#define AST 68   // As_T row stride (floats): even (8B align) + bank-spread

// ---- device scratch (static allocation only) ----
__device__ __half g_hA[NM][NN * DD];     // fp16 ping
__device__ __half g_hB[NM][NN * DD];     // fp16 pong
__device__ float g_dinv[NM][NN];
__device__ int   g_deg[NM][NN];
__device__ int   g_rowstart[NM][NN + 1];
__device__ int   g_cursor[NM][NN];
__device__ int2  g_csr[NM][NE];          // {src, bitcast(dinv[src])}
__device__ int   g_bsum[NM * 256];
__device__ int   g_boff[NM * 256];

// ---- f32x2 packed helpers ----
__device__ __forceinline__ unsigned long long d_bcast2(float x) {
    unsigned long long r;
    asm("mov.b64 %0, {%1, %1};" : "=l"(r) : "f"(x));
    return r;
}
__device__ __forceinline__ void d_fma2(unsigned long long& d,
                                       unsigned long long a,
                                       unsigned long long b) {
    asm("fma.rn.f32x2 %0, %1, %2, %3;" : "=l"(d) : "l"(a), "l"(b), "l"(d));
}
__device__ __forceinline__ float2 d_unpack2(unsigned long long v) {
    float2 f;
    asm("mov.b64 {%0, %1}, %2;" : "=f"(f.x), "=f"(f.y) : "l"(v));
    return f;
}

// ---------------- CSR build ----------------
__global__ void k_zero_deg() {
    int i = blockIdx.x * blockDim.x + threadIdx.x;   // [0, 2*NN)
    ((int*)g_deg)[i] = 0;
}

__global__ void k_count(const int* __restrict__ ei) {
    int gi = blockIdx.x * blockDim.x + threadIdx.x;  // [0, 2*NE)
    int m = gi >> 20;                                // NE = 2^20
    int e = gi & (NE - 1);
    int d = ei[(size_t)m * 2 * NE + NE + e] & (NN - 1);
    atomicAdd(&g_deg[m][d], 1);
}

__global__ void k_blocksum() {
    __shared__ int red[256];
    int m = blockIdx.x >> 8;
    int cb = blockIdx.x & 255;
    int node = cb * 256 + threadIdx.x;
    int d = g_deg[m][node];
    g_dinv[m][node] = rsqrtf((float)d + 1.0f);
    red[threadIdx.x] = d;
    __syncthreads();
    for (int off = 128; off > 0; off >>= 1) {
        if (threadIdx.x < off) red[threadIdx.x] += red[threadIdx.x + off];
        __syncthreads();
    }
    if (threadIdx.x == 0) g_bsum[m * 256 + cb] = red[0];
}

__global__ void k_scanb() {
    __shared__ int s[256];
    int t = threadIdx.x;
    int v = g_bsum[blockIdx.x * 256 + t];
    s[t] = v;
    __syncthreads();
    for (int off = 1; off < 256; off <<= 1) {
        int u = (t >= off) ? s[t - off] : 0;
        __syncthreads();
        s[t] += u;
        __syncthreads();
    }
    g_boff[blockIdx.x * 256 + t] = s[t] - v;
}

__global__ void k_rowstart() {
    __shared__ int s[256];
    int m = blockIdx.x >> 8;
    int cb = blockIdx.x & 255;
    int t = threadIdx.x;
    int node = cb * 256 + t;
    int d = g_deg[m][node];
    s[t] = d;
    __syncthreads();
    for (int off = 1; off < 256; off <<= 1) {
        int u = (t >= off) ? s[t - off] : 0;
        __syncthreads();
        s[t] += u;
        __syncthreads();
    }
    int rs = g_boff[m * 256 + cb] + s[t] - d;
    g_rowstart[m][node] = rs;
    g_cursor[m][node] = rs;
    if (node == NN - 1) g_rowstart[m][NN] = rs + d;
}

__global__ void k_fill(const int* __restrict__ ei) {
    int gi = blockIdx.x * blockDim.x + threadIdx.x;
    int m = gi >> 20;
    int e = gi & (NE - 1);
    int s = ei[(size_t)m * 2 * NE + e] & (NN - 1);
    int d = ei[(size_t)m * 2 * NE + NE + e] & (NN - 1);
    int pos = atomicAdd(&g_cursor[m][d], 1);
    g_csr[m][pos] = make_int2(s, __float_as_int(g_dinv[m][s]));
}

// ---------------- fused layer: out = maybe_relu( (A_norm @ h) @ W + b ) ----------------
template<bool IN16, bool OUT16>
__global__ __launch_bounds__(256) void k_layer(
    const void* __restrict__ hin,
    void* __restrict__ hout,
    const float* __restrict__ Wbase,
    const float* __restrict__ bbase,
    int j, int relu)
{
    __shared__ float As[64 * AST];   // TRANSPOSED: As[k][m]
    __shared__ float Ws[64 * 64];

    int tid = threadIdx.x;
    int m = blockIdx.x >> 10;
    int tile = blockIdx.x & 1023;

    const float* Wj = Wbase + ((size_t)m * NL + j) * DD * DD;
    const float* bj = bbase + ((size_t)m * NL + j) * DD;

    // load W tile
    {
        const float4* W4 = (const float4*)Wj;
        float4* Ws4 = (float4*)Ws;
#pragma unroll
        for (int k = 0; k < 4; k++) Ws4[tid + k * 256] = W4[tid + k * 256];
    }

    // ---- Phase 1: aggregate 64 rows of h into As_T ----
    {
        int t = tid & 15;        // feature lane (4 features = 4 k's)
        int grp = tid >> 4;      // 16 node groups
        const int2* csr = g_csr[m];

        const float4* h4 = (const float4*)hin + (IN16 ? 0 : (size_t)m * NN * 16);
        const uint2*  h2 = (const uint2*)hin + (IN16 ? (size_t)m * NN * 16 : 0);

#pragma unroll
        for (int g = 0; g < 4; g++) {
            int nl = g * 16 + grp;
            int n = tile * 64 + nl;
            int beg = g_rowstart[m][n];
            int end = g_rowstart[m][n + 1];

            float4 acc = make_float4(0.f, 0.f, 0.f, 0.f);
            int e = beg;
            for (; e + 3 < end; e += 4) {
                int2 s0 = csr[e];
                int2 s1 = csr[e + 1];
                int2 s2 = csr[e + 2];
                int2 s3 = csr[e + 3];
                float4 v0, v1, v2, v3;
                if (IN16) {
                    uint2 r0 = h2[(size_t)s0.x * 16 + t];
                    uint2 r1 = h2[(size_t)s1.x * 16 + t];
                    uint2 r2 = h2[(size_t)s2.x * 16 + t];
                    uint2 r3 = h2[(size_t)s3.x * 16 + t];
                    float2 a, bq;
                    a = __half22float2(*(half2*)&r0.x); bq = __half22float2(*(half2*)&r0.y);
                    v0 = make_float4(a.x, a.y, bq.x, bq.y);
                    a = __half22float2(*(half2*)&r1.x); bq = __half22float2(*(half2*)&r1.y);
                    v1 = make_float4(a.x, a.y, bq.x, bq.y);
                    a = __half22float2(*(half2*)&r2.x); bq = __half22float2(*(half2*)&r2.y);
                    v2 = make_float4(a.x, a.y, bq.x, bq.y);
                    a = __half22float2(*(half2*)&r3.x); bq = __half22float2(*(half2*)&r3.y);
                    v3 = make_float4(a.x, a.y, bq.x, bq.y);
                } else {
                    v0 = h4[(size_t)s0.x * 16 + t];
                    v1 = h4[(size_t)s1.x * 16 + t];
                    v2 = h4[(size_t)s2.x * 16 + t];
                    v3 = h4[(size_t)s3.x * 16 + t];
                }
                float w0 = __int_as_float(s0.y);
                float w1 = __int_as_float(s1.y);
                float w2 = __int_as_float(s2.y);
                float w3 = __int_as_float(s3.y);
                acc.x += w0 * v0.x; acc.y += w0 * v0.y; acc.z += w0 * v0.z; acc.w += w0 * v0.w;
                acc.x += w1 * v1.x; acc.y += w1 * v1.y; acc.z += w1 * v1.z; acc.w += w1 * v1.w;
                acc.x += w2 * v2.x; acc.y += w2 * v2.y; acc.z += w2 * v2.z; acc.w += w2 * v2.w;
                acc.x += w3 * v3.x; acc.y += w3 * v3.y; acc.z += w3 * v3.z; acc.w += w3 * v3.w;
            }
            for (; e < end; e++) {
                int2 sw = csr[e];
                float w = __int_as_float(sw.y);
                float4 v;
                if (IN16) {
                    uint2 r0 = h2[(size_t)sw.x * 16 + t];
                    float2 a = __half22float2(*(half2*)&r0.x);
                    float2 bq = __half22float2(*(half2*)&r0.y);
                    v = make_float4(a.x, a.y, bq.x, bq.y);
                } else {
                    v = h4[(size_t)sw.x * 16 + t];
                }
                acc.x += w * v.x; acc.y += w * v.y; acc.z += w * v.z; acc.w += w * v.w;
            }

            float di = g_dinv[m][n];
            float d2 = di * di;
            float4 self;
            if (IN16) {
                uint2 r0 = h2[(size_t)n * 16 + t];
                float2 a = __half22float2(*(half2*)&r0.x);
                float2 bq = __half22float2(*(half2*)&r0.y);
                self = make_float4(a.x, a.y, bq.x, bq.y);
            } else {
                self = h4[(size_t)n * 16 + t];
            }
            // transposed store: As[k][nl], k = t*4 + c
            As[(t * 4 + 0) * AST + nl] = di * acc.x + d2 * self.x;
            As[(t * 4 + 1) * AST + nl] = di * acc.y + d2 * self.y;
            As[(t * 4 + 2) * AST + nl] = di * acc.z + d2 * self.z;
            As[(t * 4 + 3) * AST + nl] = di * acc.w + d2 * self.w;
        }
    }
    __syncthreads();

    // ---- Phase 2: D = As^T @ W + b (+ReLU), packed f32x2 FMAs ----
    {
        int tx = tid & 15;   // n group (4 cols)
        int ty = tid >> 4;   // m group (4 rows)

        unsigned long long acc[2][4];  // [m-pair][n] ; pair p = rows (ty*4+2p, ty*4+2p+1)
#pragma unroll
        for (int p = 0; p < 2; p++)
#pragma unroll
            for (int n = 0; n < 4; n++) acc[p][n] = 0ull;

#pragma unroll
        for (int k = 0; k < 64; k++) {
            float4 wv = *(const float4*)&Ws[k * 64 + tx * 4];
            unsigned long long wp0 = d_bcast2(wv.x);
            unsigned long long wp1 = d_bcast2(wv.y);
            unsigned long long wp2 = d_bcast2(wv.z);
            unsigned long long wp3 = d_bcast2(wv.w);
            unsigned long long a0 = *(const unsigned long long*)&As[k * AST + ty * 4];
            unsigned long long a1 = *(const unsigned long long*)&As[k * AST + ty * 4 + 2];
            d_fma2(acc[0][0], a0, wp0); d_fma2(acc[1][0], a1, wp0);
            d_fma2(acc[0][1], a0, wp1); d_fma2(acc[1][1], a1, wp1);
            d_fma2(acc[0][2], a0, wp2); d_fma2(acc[1][2], a1, wp2);
            d_fma2(acc[0][3], a0, wp3); d_fma2(acc[1][3], a1, wp3);
        }

        float4 bb = ((const float4*)bj)[tx];
#pragma unroll
        for (int p = 0; p < 2; p++) {
            float2 u0 = d_unpack2(acc[p][0]);
            float2 u1 = d_unpack2(acc[p][1]);
            float2 u2 = d_unpack2(acc[p][2]);
            float2 u3 = d_unpack2(acc[p][3]);
            float4 r0 = make_float4(u0.x + bb.x, u1.x + bb.y, u2.x + bb.z, u3.x + bb.w);
            float4 r1 = make_float4(u0.y + bb.x, u1.y + bb.y, u2.y + bb.z, u3.y + bb.w);
            if (relu) {
                r0.x = fmaxf(r0.x, 0.f); r0.y = fmaxf(r0.y, 0.f);
                r0.z = fmaxf(r0.z, 0.f); r0.w = fmaxf(r0.w, 0.f);
                r1.x = fmaxf(r1.x, 0.f); r1.y = fmaxf(r1.y, 0.f);
                r1.z = fmaxf(r1.z, 0.f); r1.w = fmaxf(r1.w, 0.f);
            }
            size_t row0 = (size_t)tile * 64 + ty * 4 + 2 * p;
            if (OUT16) {
                half2 p00 = __floats2half2_rn(r0.x, r0.y);
                half2 p01 = __floats2half2_rn(r0.z, r0.w);
                half2 p10 = __floats2half2_rn(r1.x, r1.y);
                half2 p11 = __floats2half2_rn(r1.z, r1.w);
                uint2 o0, o1;
                o0.x = *(unsigned int*)&p00; o0.y = *(unsigned int*)&p01;
                o1.x = *(unsigned int*)&p10; o1.y = *(unsigned int*)&p11;
                ((uint2*)hout)[((size_t)m * NN + row0) * 16 + tx] = o0;
                ((uint2*)hout)[((size_t)m * NN + row0 + 1) * 16 + tx] = o1;
            } else {
                ((float4*)hout)[((size_t)m * NN + row0) * 16 + tx] = r0;
                ((float4*)hout)[((size_t)m * NN + row0 + 1) * 16 + tx] = r1;
            }
        }
    }
}

// ---------------- launcher ----------------
extern "C" void kernel_launch(void* const* d_in, const int* in_sizes, int n_in,
                              void* d_out, int out_size) {
    const float* x  = (const float*)d_in[0];
    const int*   ei = (const int*)d_in[1];   // int32 (JAX demotes int64)
    const float* W  = (const float*)d_in[2];
    const float* b  = (const float*)d_in[3];
    float*       out = (float*)d_out;

    void* hA;
    void* hB;
    cudaGetSymbolAddress(&hA, g_hA);
    cudaGetSymbolAddress(&hB, g_hB);

    // ---- CSR build for both members ----
    k_zero_deg<<<2 * NN / 256, 256>>>();
    k_count<<<2 * NE / 256, 256>>>(ei);
    k_blocksum<<<512, 256>>>();
    k_scanb<<<2, 256>>>();
    k_rowstart<<<512, 256>>>();
    k_fill<<<2 * NE / 256, 256>>>(ei);

    // ---- 12 fused layers, both members per launch ----
    void* bufs[2] = { hA, hB };
    k_layer<false, true><<<2048, 256>>>(x, bufs[0], W, b, 0, 1);
    const void* in = bufs[0];
    for (int j = 1; j <= 10; j++) {
        void* outp = bufs[j & 1];
        k_layer<true, true><<<2048, 256>>>(in, outp, W, b, j, 1);
        in = outp;
    }
    k_layer<true, false><<<2048, 256>>>(in, out, W, b, 11, 0);
}

// round 11
// speedup vs baseline: 1.7588x; 1.0793x over previous
#include <cuda_runtime.h>
#include <cuda_fp16.h>

#define NN 65536
#define NE 1048576
#define DD 64
#define NL 12
#define NM 2
#define AST 68   // As_T row stride (floats)

// ---- device scratch (static allocation only) ----
__device__ __half g_hA[NM][NN * DD];     // fp16 ping
__device__ __half g_hB[NM][NN * DD];     // fp16 pong
__device__ float g_dinv[NM][NN];
__device__ int   g_deg[NM][NN];
__device__ int   g_rowstart[NM][NN + 1];
__device__ int   g_cursor[NM][NN];
__device__ int2  g_csr[NM][NE];          // {src, bitcast(dinv[src])}
__device__ int   g_bsum[NM * 256];
__device__ int   g_boff[NM * 256];

// ---- f32x2 packed helpers ----
__device__ __forceinline__ unsigned long long d_bcast2(float x) {
    unsigned long long r;
    asm("mov.b64 %0, {%1, %1};" : "=l"(r) : "f"(x));
    return r;
}
__device__ __forceinline__ void d_fma2(unsigned long long& d,
                                       unsigned long long a,
                                       unsigned long long b) {
    asm("fma.rn.f32x2 %0, %1, %2, %3;" : "=l"(d) : "l"(a), "l"(b), "l"(d));
}
__device__ __forceinline__ float2 d_unpack2(unsigned long long v) {
    float2 f;
    asm("mov.b64 {%0, %1}, %2;" : "=f"(f.x), "=f"(f.y) : "l"(v));
    return f;
}

// ---------------- CSR build ----------------
__global__ void k_zero_deg() {
    int i = blockIdx.x * blockDim.x + threadIdx.x;
    ((int*)g_deg)[i] = 0;
}

__global__ void k_count(const int* __restrict__ ei) {
    int gi = blockIdx.x * blockDim.x + threadIdx.x;
    int m = gi >> 20;
    int e = gi & (NE - 1);
    int d = ei[(size_t)m * 2 * NE + NE + e] & (NN - 1);
    atomicAdd(&g_deg[m][d], 1);
}

__global__ void k_blocksum() {
    __shared__ int red[256];
    int m = blockIdx.x >> 8;
    int cb = blockIdx.x & 255;
    int node = cb * 256 + threadIdx.x;
    int d = g_deg[m][node];
    g_dinv[m][node] = rsqrtf((float)d + 1.0f);
    red[threadIdx.x] = d;
    __syncthreads();
    for (int off = 128; off > 0; off >>= 1) {
        if (threadIdx.x < off) red[threadIdx.x] += red[threadIdx.x + off];
        __syncthreads();
    }
    if (threadIdx.x == 0) g_bsum[m * 256 + cb] = red[0];
}

__global__ void k_scanb() {
    __shared__ int s[256];
    int t = threadIdx.x;
    int v = g_bsum[blockIdx.x * 256 + t];
    s[t] = v;
    __syncthreads();
    for (int off = 1; off < 256; off <<= 1) {
        int u = (t >= off) ? s[t - off] : 0;
        __syncthreads();
        s[t] += u;
        __syncthreads();
    }
    g_boff[blockIdx.x * 256 + t] = s[t] - v;
}

__global__ void k_rowstart() {
    __shared__ int s[256];
    int m = blockIdx.x >> 8;
    int cb = blockIdx.x & 255;
    int t = threadIdx.x;
    int node = cb * 256 + t;
    int d = g_deg[m][node];
    s[t] = d;
    __syncthreads();
    for (int off = 1; off < 256; off <<= 1) {
        int u = (t >= off) ? s[t - off] : 0;
        __syncthreads();
        s[t] += u;
        __syncthreads();
    }
    int rs = g_boff[m * 256 + cb] + s[t] - d;
    g_rowstart[m][node] = rs;
    g_cursor[m][node] = rs;
    if (node == NN - 1) g_rowstart[m][NN] = rs + d;
}

__global__ void k_fill(const int* __restrict__ ei) {
    int gi = blockIdx.x * blockDim.x + threadIdx.x;
    int m = gi >> 20;
    int e = gi & (NE - 1);
    int s = ei[(size_t)m * 2 * NE + e] & (NN - 1);
    int d = ei[(size_t)m * 2 * NE + NE + e] & (NN - 1);
    int pos = atomicAdd(&g_cursor[m][d], 1);
    g_csr[m][pos] = make_int2(s, __float_as_int(g_dinv[m][s]));
}

// ---------------- fused layer ----------------
// Phase 1: 8 lanes/node, LDG.128 gathers, int4 CSR loads. Phase 2: f32x2 GEMM.
template<bool IN16, bool OUT16>
__global__ __launch_bounds__(256) void k_layer(
    const void* __restrict__ hin,
    void* __restrict__ hout,
    const float* __restrict__ Wbase,
    const float* __restrict__ bbase,
    int j, int relu)
{
    __shared__ float As[64 * AST];   // TRANSPOSED: As[k][m]
    __shared__ float Ws[64 * 64];

    int tid = threadIdx.x;
    int m = blockIdx.x >> 10;
    int tile = blockIdx.x & 1023;

    const float* Wj = Wbase + ((size_t)m * NL + j) * DD * DD;
    const float* bj = bbase + ((size_t)m * NL + j) * DD;

    // load W tile
    {
        const float4* W4 = (const float4*)Wj;
        float4* Ws4 = (float4*)Ws;
#pragma unroll
        for (int k = 0; k < 4; k++) Ws4[tid + k * 256] = W4[tid + k * 256];
    }

    // ---- Phase 1: aggregate 64 rows of h into As_T ----
    {
        int t = tid & 7;         // 16-byte lane (8 features)
        int grp = tid >> 3;      // 32 node groups
        const int2* csr = g_csr[m];

        // fp16 rows: 128 B = 8 uint4 ; fp32 rows: 256 B = 16 float4
        const uint4*  h16 = (const uint4*)hin + (IN16 ? (size_t)m * NN * 8 : 0);
        const float4* h32 = (const float4*)hin + (IN16 ? 0 : (size_t)m * NN * 16);

#pragma unroll
        for (int g = 0; g < 2; g++) {
            int nl = g * 32 + grp;
            int n = tile * 64 + nl;
            int beg = g_rowstart[m][n];
            int end = g_rowstart[m][n + 1];

            float acc[8];
#pragma unroll
            for (int c = 0; c < 8; c++) acc[c] = 0.f;

            int e = beg;

            // single-edge processor (prologue / tail)
            auto one = [&](int ee) {
                int2 sw = csr[ee];
                float w = __int_as_float(sw.y);
                if (IN16) {
                    uint4 q = h16[(size_t)sw.x * 8 + t];
                    float2 f0 = __half22float2(*(half2*)&q.x);
                    float2 f1 = __half22float2(*(half2*)&q.y);
                    float2 f2 = __half22float2(*(half2*)&q.z);
                    float2 f3 = __half22float2(*(half2*)&q.w);
                    acc[0] += w * f0.x; acc[1] += w * f0.y;
                    acc[2] += w * f1.x; acc[3] += w * f1.y;
                    acc[4] += w * f2.x; acc[5] += w * f2.y;
                    acc[6] += w * f3.x; acc[7] += w * f3.y;
                } else {
                    float4 p0 = h32[(size_t)sw.x * 16 + 2 * t];
                    float4 p1 = h32[(size_t)sw.x * 16 + 2 * t + 1];
                    acc[0] += w * p0.x; acc[1] += w * p0.y;
                    acc[2] += w * p0.z; acc[3] += w * p0.w;
                    acc[4] += w * p1.x; acc[5] += w * p1.y;
                    acc[6] += w * p1.z; acc[7] += w * p1.w;
                }
            };

            if ((e & 1) && e < end) { one(e); e++; }

            // 4-edge main body: two int4 CSR loads (e even), 4 h-row loads in flight
            for (; e + 3 < end; e += 4) {
                int4 c01 = *(const int4*)&csr[e];       // {s0, w0, s1, w1}
                int4 c23 = *(const int4*)&csr[e + 2];   // {s2, w2, s3, w3}
                float w0 = __int_as_float(c01.y);
                float w1 = __int_as_float(c01.w);
                float w2 = __int_as_float(c23.y);
                float w3 = __int_as_float(c23.w);
                if (IN16) {
                    uint4 q0 = h16[(size_t)c01.x * 8 + t];
                    uint4 q1 = h16[(size_t)c01.z * 8 + t];
                    uint4 q2 = h16[(size_t)c23.x * 8 + t];
                    uint4 q3 = h16[(size_t)c23.z * 8 + t];
                    float2 f;
                    f = __half22float2(*(half2*)&q0.x); acc[0] += w0 * f.x; acc[1] += w0 * f.y;
                    f = __half22float2(*(half2*)&q0.y); acc[2] += w0 * f.x; acc[3] += w0 * f.y;
                    f = __half22float2(*(half2*)&q0.z); acc[4] += w0 * f.x; acc[5] += w0 * f.y;
                    f = __half22float2(*(half2*)&q0.w); acc[6] += w0 * f.x; acc[7] += w0 * f.y;
                    f = __half22float2(*(half2*)&q1.x); acc[0] += w1 * f.x; acc[1] += w1 * f.y;
                    f = __half22float2(*(half2*)&q1.y); acc[2] += w1 * f.x; acc[3] += w1 * f.y;
                    f = __half22float2(*(half2*)&q1.z); acc[4] += w1 * f.x; acc[5] += w1 * f.y;
                    f = __half22float2(*(half2*)&q1.w); acc[6] += w1 * f.x; acc[7] += w1 * f.y;
                    f = __half22float2(*(half2*)&q2.x); acc[0] += w2 * f.x; acc[1] += w2 * f.y;
                    f = __half22float2(*(half2*)&q2.y); acc[2] += w2 * f.x; acc[3] += w2 * f.y;
                    f = __half22float2(*(half2*)&q2.z); acc[4] += w2 * f.x; acc[5] += w2 * f.y;
                    f = __half22float2(*(half2*)&q2.w); acc[6] += w2 * f.x; acc[7] += w2 * f.y;
                    f = __half22float2(*(half2*)&q3.x); acc[0] += w3 * f.x; acc[1] += w3 * f.y;
                    f = __half22float2(*(half2*)&q3.y); acc[2] += w3 * f.x; acc[3] += w3 * f.y;
                    f = __half22float2(*(half2*)&q3.z); acc[4] += w3 * f.x; acc[5] += w3 * f.y;
                    f = __half22float2(*(half2*)&q3.w); acc[6] += w3 * f.x; acc[7] += w3 * f.y;
                } else {
                    float4 p00 = h32[(size_t)c01.x * 16 + 2 * t];
                    float4 p01 = h32[(size_t)c01.x * 16 + 2 * t + 1];
                    float4 p10 = h32[(size_t)c01.z * 16 + 2 * t];
                    float4 p11 = h32[(size_t)c01.z * 16 + 2 * t + 1];
                    float4 p20 = h32[(size_t)c23.x * 16 + 2 * t];
                    float4 p21 = h32[(size_t)c23.x * 16 + 2 * t + 1];
                    float4 p30 = h32[(size_t)c23.z * 16 + 2 * t];
                    float4 p31 = h32[(size_t)c23.z * 16 + 2 * t + 1];
                    acc[0] += w0 * p00.x; acc[1] += w0 * p00.y; acc[2] += w0 * p00.z; acc[3] += w0 * p00.w;
                    acc[4] += w0 * p01.x; acc[5] += w0 * p01.y; acc[6] += w0 * p01.z; acc[7] += w0 * p01.w;
                    acc[0] += w1 * p10.x; acc[1] += w1 * p10.y; acc[2] += w1 * p10.z; acc[3] += w1 * p10.w;
                    acc[4] += w1 * p11.x; acc[5] += w1 * p11.y; acc[6] += w1 * p11.z; acc[7] += w1 * p11.w;
                    acc[0] += w2 * p20.x; acc[1] += w2 * p20.y; acc[2] += w2 * p20.z; acc[3] += w2 * p20.w;
                    acc[4] += w2 * p21.x; acc[5] += w2 * p21.y; acc[6] += w2 * p21.z; acc[7] += w2 * p21.w;
                    acc[0] += w3 * p30.x; acc[1] += w3 * p30.y; acc[2] += w3 * p30.z; acc[3] += w3 * p30.w;
                    acc[4] += w3 * p31.x; acc[5] += w3 * p31.y; acc[6] += w3 * p31.z; acc[7] += w3 * p31.w;
                }
            }
            for (; e < end; e++) one(e);

            float di = g_dinv[m][n];
            float d2 = di * di;
            float selfv[8];
            if (IN16) {
                uint4 q = h16[(size_t)n * 8 + t];
                float2 f0 = __half22float2(*(half2*)&q.x);
                float2 f1 = __half22float2(*(half2*)&q.y);
                float2 f2 = __half22float2(*(half2*)&q.z);
                float2 f3 = __half22float2(*(half2*)&q.w);
                selfv[0] = f0.x; selfv[1] = f0.y; selfv[2] = f1.x; selfv[3] = f1.y;
                selfv[4] = f2.x; selfv[5] = f2.y; selfv[6] = f3.x; selfv[7] = f3.y;
            } else {
                float4 p0 = h32[(size_t)n * 16 + 2 * t];
                float4 p1 = h32[(size_t)n * 16 + 2 * t + 1];
                selfv[0] = p0.x; selfv[1] = p0.y; selfv[2] = p0.z; selfv[3] = p0.w;
                selfv[4] = p1.x; selfv[5] = p1.y; selfv[6] = p1.z; selfv[7] = p1.w;
            }
            int k0 = t * 8;
#pragma unroll
            for (int c = 0; c < 8; c++)
                As[(k0 + c) * AST + nl] = di * acc[c] + d2 * selfv[c];
        }
    }
    __syncthreads();

    // ---- Phase 2: D = As^T @ W + b (+ReLU), packed f32x2 FMAs ----
    {
        int tx = tid & 15;   // n group (4 cols)
        int ty = tid >> 4;   // m group (4 rows)

        unsigned long long acc[2][4];
#pragma unroll
        for (int p = 0; p < 2; p++)
#pragma unroll
            for (int n = 0; n < 4; n++) acc[p][n] = 0ull;

#pragma unroll
        for (int k = 0; k < 64; k++) {
            float4 wv = *(const float4*)&Ws[k * 64 + tx * 4];
            unsigned long long wp0 = d_bcast2(wv.x);
            unsigned long long wp1 = d_bcast2(wv.y);
            unsigned long long wp2 = d_bcast2(wv.z);
            unsigned long long wp3 = d_bcast2(wv.w);
            unsigned long long a0 = *(const unsigned long long*)&As[k * AST + ty * 4];
            unsigned long long a1 = *(const unsigned long long*)&As[k * AST + ty * 4 + 2];
            d_fma2(acc[0][0], a0, wp0); d_fma2(acc[1][0], a1, wp0);
            d_fma2(acc[0][1], a0, wp1); d_fma2(acc[1][1], a1, wp1);
            d_fma2(acc[0][2], a0, wp2); d_fma2(acc[1][2], a1, wp2);
            d_fma2(acc[0][3], a0, wp3); d_fma2(acc[1][3], a1, wp3);
        }

        float4 bb = ((const float4*)bj)[tx];
#pragma unroll
        for (int p = 0; p < 2; p++) {
            float2 u0 = d_unpack2(acc[p][0]);
            float2 u1 = d_unpack2(acc[p][1]);
            float2 u2 = d_unpack2(acc[p][2]);
            float2 u3 = d_unpack2(acc[p][3]);
            float4 r0 = make_float4(u0.x + bb.x, u1.x + bb.y, u2.x + bb.z, u3.x + bb.w);
            float4 r1 = make_float4(u0.y + bb.x, u1.y + bb.y, u2.y + bb.z, u3.y + bb.w);
            if (relu) {
                r0.x = fmaxf(r0.x, 0.f); r0.y = fmaxf(r0.y, 0.f);
                r0.z = fmaxf(r0.z, 0.f); r0.w = fmaxf(r0.w, 0.f);
                r1.x = fmaxf(r1.x, 0.f); r1.y = fmaxf(r1.y, 0.f);
                r1.z = fmaxf(r1.z, 0.f); r1.w = fmaxf(r1.w, 0.f);
            }
            size_t row0 = (size_t)tile * 64 + ty * 4 + 2 * p;
            if (OUT16) {
                half2 p00 = __floats2half2_rn(r0.x, r0.y);
                half2 p01 = __floats2half2_rn(r0.z, r0.w);
                half2 p10 = __floats2half2_rn(r1.x, r1.y);
                half2 p11 = __floats2half2_rn(r1.z, r1.w);
                uint2 o0, o1;
                o0.x = *(unsigned int*)&p00; o0.y = *(unsigned int*)&p01;
                o1.x = *(unsigned int*)&p10; o1.y = *(unsigned int*)&p11;
                ((uint2*)hout)[((size_t)m * NN + row0) * 16 + tx] = o0;
                ((uint2*)hout)[((size_t)m * NN + row0 + 1) * 16 + tx] = o1;
            } else {
                ((float4*)hout)[((size_t)m * NN + row0) * 16 + tx] = r0;
                ((float4*)hout)[((size_t)m * NN + row0 + 1) * 16 + tx] = r1;
            }
        }
    }
}

// ---------------- launcher ----------------
extern "C" void kernel_launch(void* const* d_in, const int* in_sizes, int n_in,
                              void* d_out, int out_size) {
    const float* x  = (const float*)d_in[0];
    const int*   ei = (const int*)d_in[1];   // int32 (JAX demotes int64)
    const float* W  = (const float*)d_in[2];
    const float* b  = (const float*)d_in[3];
    float*       out = (float*)d_out;

    void* hA;
    void* hB;
    cudaGetSymbolAddress(&hA, g_hA);
    cudaGetSymbolAddress(&hB, g_hB);

    // ---- CSR build for both members ----
    k_zero_deg<<<2 * NN / 256, 256>>>();
    k_count<<<2 * NE / 256, 256>>>(ei);
    k_blocksum<<<512, 256>>>();
    k_scanb<<<2, 256>>>();
    k_rowstart<<<512, 256>>>();
    k_fill<<<2 * NE / 256, 256>>>(ei);

    // ---- 12 fused layers, both members per launch ----
    void* bufs[2] = { hA, hB };
    k_layer<false, true><<<2048, 256>>>(x, bufs[0], W, b, 0, 1);
    const void* in = bufs[0];
    for (int j = 1; j <= 10; j++) {
        void* outp = bufs[j & 1];
        k_layer<true, true><<<2048, 256>>>(in, outp, W, b, j, 1);
        in = outp;
    }
    k_layer<true, false><<<2048, 256>>>(in, out, W, b, 11, 0);
}

// round 12
// speedup vs baseline: 1.8008x; 1.0239x over previous
#include <cuda_runtime.h>
#include <cuda_fp16.h>

#define NN 65536
#define NE 1048576
#define DD 64
#define NL 12
#define NM 2
#define AST 68   // As_T row stride (floats)

// ---- device scratch (static allocation only) ----
__device__ __half g_hA[NM][NN * DD];     // fp16 ping
__device__ __half g_hB[NM][NN * DD];     // fp16 pong
__device__ float g_dinv[NM][NN];
__device__ int   g_deg[NM][NN];
__device__ int   g_rowstart[NM][NN + 1];
__device__ int   g_cursor[NM][NN];
__device__ int2  g_csr[NM][NE];          // {src, bitcast(dinv[src])}
__device__ int   g_bsum[NM * 256];
__device__ int   g_boff[NM * 256];

// ---- f32x2 packed helpers ----
__device__ __forceinline__ unsigned long long d_bcast2(float x) {
    unsigned long long r;
    asm("mov.b64 %0, {%1, %1};" : "=l"(r) : "f"(x));
    return r;
}
__device__ __forceinline__ void d_fma2(unsigned long long& d,
                                       unsigned long long a,
                                       unsigned long long b) {
    asm("fma.rn.f32x2 %0, %1, %2, %3;" : "=l"(d) : "l"(a), "l"(b), "l"(d));
}
__device__ __forceinline__ float2 d_unpack2(unsigned long long v) {
    float2 f;
    asm("mov.b64 {%0, %1}, %2;" : "=f"(f.x), "=f"(f.y) : "l"(v));
    return f;
}

// ---------------- CSR build ----------------
__global__ void k_zero_deg() {
    int i = blockIdx.x * blockDim.x + threadIdx.x;
    ((int*)g_deg)[i] = 0;
}

__global__ void k_count(const int* __restrict__ ei) {
    int gi = blockIdx.x * blockDim.x + threadIdx.x;
    int m = gi >> 20;
    int e = gi & (NE - 1);
    int d = ei[(size_t)m * 2 * NE + NE + e] & (NN - 1);
    atomicAdd(&g_deg[m][d], 1);
}

__global__ void k_blocksum() {
    __shared__ int red[256];
    int m = blockIdx.x >> 8;
    int cb = blockIdx.x & 255;
    int node = cb * 256 + threadIdx.x;
    int d = g_deg[m][node];
    g_dinv[m][node] = rsqrtf((float)d + 1.0f);
    red[threadIdx.x] = d;
    __syncthreads();
    for (int off = 128; off > 0; off >>= 1) {
        if (threadIdx.x < off) red[threadIdx.x] += red[threadIdx.x + off];
        __syncthreads();
    }
    if (threadIdx.x == 0) g_bsum[m * 256 + cb] = red[0];
}

__global__ void k_scanb() {
    __shared__ int s[256];
    int t = threadIdx.x;
    int v = g_bsum[blockIdx.x * 256 + t];
    s[t] = v;
    __syncthreads();
    for (int off = 1; off < 256; off <<= 1) {
        int u = (t >= off) ? s[t - off] : 0;
        __syncthreads();
        s[t] += u;
        __syncthreads();
    }
    g_boff[blockIdx.x * 256 + t] = s[t] - v;
}

__global__ void k_rowstart() {
    __shared__ int s[256];
    int m = blockIdx.x >> 8;
    int cb = blockIdx.x & 255;
    int t = threadIdx.x;
    int node = cb * 256 + t;
    int d = g_deg[m][node];
    s[t] = d;
    __syncthreads();
    for (int off = 1; off < 256; off <<= 1) {
        int u = (t >= off) ? s[t - off] : 0;
        __syncthreads();
        s[t] += u;
        __syncthreads();
    }
    int rs = g_boff[m * 256 + cb] + s[t] - d;
    g_rowstart[m][node] = rs;
    g_cursor[m][node] = rs;
    if (node == NN - 1) g_rowstart[m][NN] = rs + d;
}

__global__ void k_fill(const int* __restrict__ ei) {
    int gi = blockIdx.x * blockDim.x + threadIdx.x;
    int m = gi >> 20;
    int e = gi & (NE - 1);
    int s = ei[(size_t)m * 2 * NE + e] & (NN - 1);
    int d = ei[(size_t)m * 2 * NE + NE + e] & (NN - 1);
    int pos = atomicAdd(&g_cursor[m][d], 1);
    g_csr[m][pos] = make_int2(s, __float_as_int(g_dinv[m][s]));
}

// ---------------- fused layer ----------------
// Phase 1: 8 lanes/node, 8-edge chunks with hoisted loads (MLP=8). Phase 2: f32x2 GEMM.
template<bool IN16, bool OUT16>
__global__ __launch_bounds__(256) void k_layer(
    const void* __restrict__ hin,
    void* __restrict__ hout,
    const float* __restrict__ Wbase,
    const float* __restrict__ bbase,
    int j, int relu)
{
    __shared__ float As[64 * AST];   // TRANSPOSED: As[k][m]
    __shared__ float Ws[64 * 64];

    int tid = threadIdx.x;
    int m = blockIdx.x >> 10;
    int tile = blockIdx.x & 1023;

    const float* Wj = Wbase + ((size_t)m * NL + j) * DD * DD;
    const float* bj = bbase + ((size_t)m * NL + j) * DD;

    // load W tile
    {
        const float4* W4 = (const float4*)Wj;
        float4* Ws4 = (float4*)Ws;
#pragma unroll
        for (int k = 0; k < 4; k++) Ws4[tid + k * 256] = W4[tid + k * 256];
    }

    // ---- Phase 1: aggregate 64 rows of h into As_T ----
    {
        int t = tid & 7;         // 16-byte lane (8 features)
        int grp = tid >> 3;      // 32 node groups
        const int2* csr = g_csr[m];

        const uint4*  h16 = (const uint4*)hin + (IN16 ? (size_t)m * NN * 8 : 0);
        const float4* h32 = (const float4*)hin + (IN16 ? 0 : (size_t)m * NN * 16);

#pragma unroll
        for (int g = 0; g < 2; g++) {
            int nl = g * 32 + grp;
            int n = tile * 64 + nl;
            int beg = g_rowstart[m][n];
            int end = g_rowstart[m][n + 1];

            float acc[8];
#pragma unroll
            for (int c = 0; c < 8; c++) acc[c] = 0.f;

            // accumulate one gathered row (fp16 path: q-register; helper inlined)
            auto accq = [&](uint4 q, float w) {
                float2 f;
                f = __half22float2(*(half2*)&q.x); acc[0] += w * f.x; acc[1] += w * f.y;
                f = __half22float2(*(half2*)&q.y); acc[2] += w * f.x; acc[3] += w * f.y;
                f = __half22float2(*(half2*)&q.z); acc[4] += w * f.x; acc[5] += w * f.y;
                f = __half22float2(*(half2*)&q.w); acc[6] += w * f.x; acc[7] += w * f.y;
            };
            auto accp = [&](float4 p0, float4 p1, float w) {
                acc[0] += w * p0.x; acc[1] += w * p0.y; acc[2] += w * p0.z; acc[3] += w * p0.w;
                acc[4] += w * p1.x; acc[5] += w * p1.y; acc[6] += w * p1.z; acc[7] += w * p1.w;
            };
            auto one = [&](int ee) {
                int2 sw = csr[ee];
                float w = __int_as_float(sw.y);
                if (IN16) accq(h16[(size_t)sw.x * 8 + t], w);
                else      accp(h32[(size_t)sw.x * 16 + 2 * t],
                               h32[(size_t)sw.x * 16 + 2 * t + 1], w);
            };

            int e = beg;
            if ((e & 1) && e < end) { one(e); e++; }   // align for int4 CSR loads

            // 8-edge chunks: 2 independent CSR int4 loads, then 8 independent row loads
            for (; e + 7 < end; e += 8) {
                int4 cA = *(const int4*)&csr[e];        // {s0,w0,s1,w1}
                int4 cB = *(const int4*)&csr[e + 2];    // {s2,w2,s3,w3}
                int4 cC = *(const int4*)&csr[e + 4];    // {s4,w4,s5,w5}
                int4 cD = *(const int4*)&csr[e + 6];    // {s6,w6,s7,w7}
                if (IN16) {
                    uint4 q0 = h16[(size_t)cA.x * 8 + t];
                    uint4 q1 = h16[(size_t)cA.z * 8 + t];
                    uint4 q2 = h16[(size_t)cB.x * 8 + t];
                    uint4 q3 = h16[(size_t)cB.z * 8 + t];
                    uint4 q4 = h16[(size_t)cC.x * 8 + t];
                    uint4 q5 = h16[(size_t)cC.z * 8 + t];
                    uint4 q6 = h16[(size_t)cD.x * 8 + t];
                    uint4 q7 = h16[(size_t)cD.z * 8 + t];
                    accq(q0, __int_as_float(cA.y));
                    accq(q1, __int_as_float(cA.w));
                    accq(q2, __int_as_float(cB.y));
                    accq(q3, __int_as_float(cB.w));
                    accq(q4, __int_as_float(cC.y));
                    accq(q5, __int_as_float(cC.w));
                    accq(q6, __int_as_float(cD.y));
                    accq(q7, __int_as_float(cD.w));
                } else {
                    float4 p00 = h32[(size_t)cA.x * 16 + 2 * t];
                    float4 p01 = h32[(size_t)cA.x * 16 + 2 * t + 1];
                    float4 p10 = h32[(size_t)cA.z * 16 + 2 * t];
                    float4 p11 = h32[(size_t)cA.z * 16 + 2 * t + 1];
                    float4 p20 = h32[(size_t)cB.x * 16 + 2 * t];
                    float4 p21 = h32[(size_t)cB.x * 16 + 2 * t + 1];
                    float4 p30 = h32[(size_t)cB.z * 16 + 2 * t];
                    float4 p31 = h32[(size_t)cB.z * 16 + 2 * t + 1];
                    accp(p00, p01, __int_as_float(cA.y));
                    accp(p10, p11, __int_as_float(cA.w));
                    accp(p20, p21, __int_as_float(cB.y));
                    accp(p30, p31, __int_as_float(cB.w));
                    float4 p40 = h32[(size_t)cC.x * 16 + 2 * t];
                    float4 p41 = h32[(size_t)cC.x * 16 + 2 * t + 1];
                    float4 p50 = h32[(size_t)cC.z * 16 + 2 * t];
                    float4 p51 = h32[(size_t)cC.z * 16 + 2 * t + 1];
                    float4 p60 = h32[(size_t)cD.x * 16 + 2 * t];
                    float4 p61 = h32[(size_t)cD.x * 16 + 2 * t + 1];
                    float4 p70 = h32[(size_t)cD.z * 16 + 2 * t];
                    float4 p71 = h32[(size_t)cD.z * 16 + 2 * t + 1];
                    accp(p40, p41, __int_as_float(cC.y));
                    accp(p50, p51, __int_as_float(cC.w));
                    accp(p60, p61, __int_as_float(cD.y));
                    accp(p70, p71, __int_as_float(cD.w));
                }
            }
            for (; e < end; e++) one(e);

            float di = g_dinv[m][n];
            float d2 = di * di;
            float selfv[8];
            if (IN16) {
                uint4 q = h16[(size_t)n * 8 + t];
                float2 f0 = __half22float2(*(half2*)&q.x);
                float2 f1 = __half22float2(*(half2*)&q.y);
                float2 f2 = __half22float2(*(half2*)&q.z);
                float2 f3 = __half22float2(*(half2*)&q.w);
                selfv[0] = f0.x; selfv[1] = f0.y; selfv[2] = f1.x; selfv[3] = f1.y;
                selfv[4] = f2.x; selfv[5] = f2.y; selfv[6] = f3.x; selfv[7] = f3.y;
            } else {
                float4 p0 = h32[(size_t)n * 16 + 2 * t];
                float4 p1 = h32[(size_t)n * 16 + 2 * t + 1];
                selfv[0] = p0.x; selfv[1] = p0.y; selfv[2] = p0.z; selfv[3] = p0.w;
                selfv[4] = p1.x; selfv[5] = p1.y; selfv[6] = p1.z; selfv[7] = p1.w;
            }
            int k0 = t * 8;
#pragma unroll
            for (int c = 0; c < 8; c++)
                As[(k0 + c) * AST + nl] = di * acc[c] + d2 * selfv[c];
        }
    }
    __syncthreads();

    // ---- Phase 2: D = As^T @ W + b (+ReLU), packed f32x2 FMAs ----
    {
        int tx = tid & 15;   // n group (4 cols)
        int ty = tid >> 4;   // m group (4 rows)

        unsigned long long acc[2][4];
#pragma unroll
        for (int p = 0; p < 2; p++)
#pragma unroll
            for (int n = 0; n < 4; n++) acc[p][n] = 0ull;

#pragma unroll
        for (int k = 0; k < 64; k++) {
            float4 wv = *(const float4*)&Ws[k * 64 + tx * 4];
            unsigned long long wp0 = d_bcast2(wv.x);
            unsigned long long wp1 = d_bcast2(wv.y);
            unsigned long long wp2 = d_bcast2(wv.z);
            unsigned long long wp3 = d_bcast2(wv.w);
            unsigned long long a0 = *(const unsigned long long*)&As[k * AST + ty * 4];
            unsigned long long a1 = *(const unsigned long long*)&As[k * AST + ty * 4 + 2];
            d_fma2(acc[0][0], a0, wp0); d_fma2(acc[1][0], a1, wp0);
            d_fma2(acc[0][1], a0, wp1); d_fma2(acc[1][1], a1, wp1);
            d_fma2(acc[0][2], a0, wp2); d_fma2(acc[1][2], a1, wp2);
            d_fma2(acc[0][3], a0, wp3); d_fma2(acc[1][3], a1, wp3);
        }

        float4 bb = ((const float4*)bj)[tx];
#pragma unroll
        for (int p = 0; p < 2; p++) {
            float2 u0 = d_unpack2(acc[p][0]);
            float2 u1 = d_unpack2(acc[p][1]);
            float2 u2 = d_unpack2(acc[p][2]);
            float2 u3 = d_unpack2(acc[p][3]);
            float4 r0 = make_float4(u0.x + bb.x, u1.x + bb.y, u2.x + bb.z, u3.x + bb.w);
            float4 r1 = make_float4(u0.y + bb.x, u1.y + bb.y, u2.y + bb.z, u3.y + bb.w);
            if (relu) {
                r0.x = fmaxf(r0.x, 0.f); r0.y = fmaxf(r0.y, 0.f);
                r0.z = fmaxf(r0.z, 0.f); r0.w = fmaxf(r0.w, 0.f);
                r1.x = fmaxf(r1.x, 0.f); r1.y = fmaxf(r1.y, 0.f);
                r1.z = fmaxf(r1.z, 0.f); r1.w = fmaxf(r1.w, 0.f);
            }
            size_t row0 = (size_t)tile * 64 + ty * 4 + 2 * p;
            if (OUT16) {
                half2 p00 = __floats2half2_rn(r0.x, r0.y);
                half2 p01 = __floats2half2_rn(r0.z, r0.w);
                half2 p10 = __floats2half2_rn(r1.x, r1.y);
                half2 p11 = __floats2half2_rn(r1.z, r1.w);
                uint2 o0, o1;
                o0.x = *(unsigned int*)&p00; o0.y = *(unsigned int*)&p01;
                o1.x = *(unsigned int*)&p10; o1.y = *(unsigned int*)&p11;
                ((uint2*)hout)[((size_t)m * NN + row0) * 16 + tx] = o0;
                ((uint2*)hout)[((size_t)m * NN + row0 + 1) * 16 + tx] = o1;
            } else {
                ((float4*)hout)[((size_t)m * NN + row0) * 16 + tx] = r0;
                ((float4*)hout)[((size_t)m * NN + row0 + 1) * 16 + tx] = r1;
            }
        }
    }
}

// ---------------- launcher ----------------
extern "C" void kernel_launch(void* const* d_in, const int* in_sizes, int n_in,
                              void* d_out, int out_size) {
    const float* x  = (const float*)d_in[0];
    const int*   ei = (const int*)d_in[1];   // int32 (JAX demotes int64)
    const float* W  = (const float*)d_in[2];
    const float* b  = (const float*)d_in[3];
    float*       out = (float*)d_out;

    void* hA;
    void* hB;
    cudaGetSymbolAddress(&hA, g_hA);
    cudaGetSymbolAddress(&hB, g_hB);

    // ---- CSR build for both members ----
    k_zero_deg<<<2 * NN / 256, 256>>>();
    k_count<<<2 * NE / 256, 256>>>(ei);
    k_blocksum<<<512, 256>>>();
    k_scanb<<<2, 256>>>();
    k_rowstart<<<512, 256>>>();
    k_fill<<<2 * NE / 256, 256>>>(ei);

    // ---- 12 fused layers, both members per launch ----
    void* bufs[2] = { hA, hB };
    k_layer<false, true><<<2048, 256>>>(x, bufs[0], W, b, 0, 1);
    const void* in = bufs[0];
    for (int j = 1; j <= 10; j++) {
        void* outp = bufs[j & 1];
        k_layer<true, true><<<2048, 256>>>(in, outp, W, b, j, 1);
        in = outp;
    }
    k_layer<true, false><<<2048, 256>>>(in, out, W, b, 11, 0);
}

// round 13
// speedup vs baseline: 1.8024x; 1.0009x over previous
#include <cuda_runtime.h>
#include <cuda_fp16.h>

#define NN 65536
#define NE 1048576
#define DD 64
#define NL 12
#define NM 2
#define AST 68   // As_T row stride (floats)

// ---- device scratch (static allocation only) ----
__device__ __half g_hA[NM][NN * DD];     // fp16 ping
__device__ __half g_hB[NM][NN * DD];     // fp16 pong
__device__ float g_dinv[NM][NN];
__device__ int   g_deg[NM][NN];
__device__ int   g_rowstart[NM][NN + 1];
__device__ int   g_cursor[NM][NN];
__device__ int2  g_csr[NM][NE];          // {src, bitcast(dinv[src])}
__device__ int   g_bsum[NM * 256];
__device__ int   g_boff[NM * 256];

// ---- f32x2 packed helpers ----
__device__ __forceinline__ unsigned long long d_bcast2(float x) {
    unsigned long long r;
    asm("mov.b64 %0, {%1, %1};" : "=l"(r) : "f"(x));
    return r;
}
__device__ __forceinline__ void d_fma2(unsigned long long& d,
                                       unsigned long long a,
                                       unsigned long long b) {
    asm("fma.rn.f32x2 %0, %1, %2, %3;" : "=l"(d) : "l"(a), "l"(b), "l"(d));
}
__device__ __forceinline__ float2 d_unpack2(unsigned long long v) {
    float2 f;
    asm("mov.b64 {%0, %1}, %2;" : "=f"(f.x), "=f"(f.y) : "l"(v));
    return f;
}

// ---------------- CSR build ----------------
__global__ void k_zero_deg() {
    int i = blockIdx.x * blockDim.x + threadIdx.x;
    ((int*)g_deg)[i] = 0;
}

__global__ void k_count(const int* __restrict__ ei) {
    int gi = blockIdx.x * blockDim.x + threadIdx.x;
    int m = gi >> 20;
    int e = gi & (NE - 1);
    int d = ei[(size_t)m * 2 * NE + NE + e] & (NN - 1);
    atomicAdd(&g_deg[m][d], 1);
}

__global__ void k_blocksum() {
    __shared__ int red[256];
    int m = blockIdx.x >> 8;
    int cb = blockIdx.x & 255;
    int node = cb * 256 + threadIdx.x;
    int d = g_deg[m][node];
    g_dinv[m][node] = rsqrtf((float)d + 1.0f);
    red[threadIdx.x] = d;
    __syncthreads();
    for (int off = 128; off > 0; off >>= 1) {
        if (threadIdx.x < off) red[threadIdx.x] += red[threadIdx.x + off];
        __syncthreads();
    }
    if (threadIdx.x == 0) g_bsum[m * 256 + cb] = red[0];
}

__global__ void k_scanb() {
    __shared__ int s[256];
    int t = threadIdx.x;
    int v = g_bsum[blockIdx.x * 256 + t];
    s[t] = v;
    __syncthreads();
    for (int off = 1; off < 256; off <<= 1) {
        int u = (t >= off) ? s[t - off] : 0;
        __syncthreads();
        s[t] += u;
        __syncthreads();
    }
    g_boff[blockIdx.x * 256 + t] = s[t] - v;
}

__global__ void k_rowstart() {
    __shared__ int s[256];
    int m = blockIdx.x >> 8;
    int cb = blockIdx.x & 255;
    int t = threadIdx.x;
    int node = cb * 256 + t;
    int d = g_deg[m][node];
    s[t] = d;
    __syncthreads();
    for (int off = 1; off < 256; off <<= 1) {
        int u = (t >= off) ? s[t - off] : 0;
        __syncthreads();
        s[t] += u;
        __syncthreads();
    }
    int rs = g_boff[m * 256 + cb] + s[t] - d;
    g_rowstart[m][node] = rs;
    g_cursor[m][node] = rs;
    if (node == NN - 1) g_rowstart[m][NN] = rs + d;
}

__global__ void k_fill(const int* __restrict__ ei) {
    int gi = blockIdx.x * blockDim.x + threadIdx.x;
    int m = gi >> 20;
    int e = gi & (NE - 1);
    int s = ei[(size_t)m * 2 * NE + e] & (NN - 1);
    int d = ei[(size_t)m * 2 * NE + NE + e] & (NN - 1);
    int pos = atomicAdd(&g_cursor[m][d], 1);
    g_csr[m][pos] = make_int2(s, __float_as_int(g_dinv[m][s]));
}

// ---------------- fused layer ----------------
// Phase 1: 8 lanes/node, 4-edge chunks (16 data regs). Phase 2: f32x2 GEMM.
// __launch_bounds__(256, 6): force 6 blocks/SM (<=42 regs) for latency hiding.
template<bool IN16, bool OUT16>
__global__ __launch_bounds__(256, 6) void k_layer(
    const void* __restrict__ hin,
    void* __restrict__ hout,
    const float* __restrict__ Wbase,
    const float* __restrict__ bbase,
    int j, int relu)
{
    __shared__ float As[64 * AST];   // TRANSPOSED: As[k][m]
    __shared__ float Ws[64 * 64];

    int tid = threadIdx.x;
    int m = blockIdx.x >> 10;
    int tile = blockIdx.x & 1023;

    const float* Wj = Wbase + ((size_t)m * NL + j) * DD * DD;
    const float* bj = bbase + ((size_t)m * NL + j) * DD;

    // load W tile
    {
        const float4* W4 = (const float4*)Wj;
        float4* Ws4 = (float4*)Ws;
#pragma unroll
        for (int k = 0; k < 4; k++) Ws4[tid + k * 256] = W4[tid + k * 256];
    }

    // ---- Phase 1: aggregate 64 rows of h into As_T ----
    {
        int t = tid & 7;         // 16-byte lane (8 features)
        int grp = tid >> 3;      // 32 node groups
        const int2* csr = g_csr[m];

        const uint4*  h16 = (const uint4*)hin + (IN16 ? (size_t)m * NN * 8 : 0);
        const float4* h32 = (const float4*)hin + (IN16 ? 0 : (size_t)m * NN * 16);

#pragma unroll
        for (int g = 0; g < 2; g++) {
            int nl = g * 32 + grp;
            int n = tile * 64 + nl;
            int beg = g_rowstart[m][n];
            int end = g_rowstart[m][n + 1];

            float acc[8];
#pragma unroll
            for (int c = 0; c < 8; c++) acc[c] = 0.f;

            auto accq = [&](uint4 q, float w) {
                float2 f;
                f = __half22float2(*(half2*)&q.x); acc[0] += w * f.x; acc[1] += w * f.y;
                f = __half22float2(*(half2*)&q.y); acc[2] += w * f.x; acc[3] += w * f.y;
                f = __half22float2(*(half2*)&q.z); acc[4] += w * f.x; acc[5] += w * f.y;
                f = __half22float2(*(half2*)&q.w); acc[6] += w * f.x; acc[7] += w * f.y;
            };
            auto accp = [&](float4 p0, float4 p1, float w) {
                acc[0] += w * p0.x; acc[1] += w * p0.y; acc[2] += w * p0.z; acc[3] += w * p0.w;
                acc[4] += w * p1.x; acc[5] += w * p1.y; acc[6] += w * p1.z; acc[7] += w * p1.w;
            };
            auto one = [&](int ee) {
                int2 sw = csr[ee];
                float w = __int_as_float(sw.y);
                if (IN16) accq(h16[(size_t)sw.x * 8 + t], w);
                else      accp(h32[(size_t)sw.x * 16 + 2 * t],
                               h32[(size_t)sw.x * 16 + 2 * t + 1], w);
            };

            int e = beg;
            if ((e & 1) && e < end) { one(e); e++; }   // align for int4 CSR loads

            // 4-edge chunks: 2 int4 CSR loads, then 4 independent row loads
            for (; e + 3 < end; e += 4) {
                int4 cA = *(const int4*)&csr[e];        // {s0,w0,s1,w1}
                int4 cB = *(const int4*)&csr[e + 2];    // {s2,w2,s3,w3}
                if (IN16) {
                    uint4 q0 = h16[(size_t)cA.x * 8 + t];
                    uint4 q1 = h16[(size_t)cA.z * 8 + t];
                    uint4 q2 = h16[(size_t)cB.x * 8 + t];
                    uint4 q3 = h16[(size_t)cB.z * 8 + t];
                    accq(q0, __int_as_float(cA.y));
                    accq(q1, __int_as_float(cA.w));
                    accq(q2, __int_as_float(cB.y));
                    accq(q3, __int_as_float(cB.w));
                } else {
                    float4 p00 = h32[(size_t)cA.x * 16 + 2 * t];
                    float4 p01 = h32[(size_t)cA.x * 16 + 2 * t + 1];
                    float4 p10 = h32[(size_t)cA.z * 16 + 2 * t];
                    float4 p11 = h32[(size_t)cA.z * 16 + 2 * t + 1];
                    accp(p00, p01, __int_as_float(cA.y));
                    accp(p10, p11, __int_as_float(cA.w));
                    float4 p20 = h32[(size_t)cB.x * 16 + 2 * t];
                    float4 p21 = h32[(size_t)cB.x * 16 + 2 * t + 1];
                    float4 p30 = h32[(size_t)cB.z * 16 + 2 * t];
                    float4 p31 = h32[(size_t)cB.z * 16 + 2 * t + 1];
                    accp(p20, p21, __int_as_float(cB.y));
                    accp(p30, p31, __int_as_float(cB.w));
                }
            }
            for (; e < end; e++) one(e);

            float di = g_dinv[m][n];
            float d2 = di * di;
            float selfv[8];
            if (IN16) {
                uint4 q = h16[(size_t)n * 8 + t];
                float2 f0 = __half22float2(*(half2*)&q.x);
                float2 f1 = __half22float2(*(half2*)&q.y);
                float2 f2 = __half22float2(*(half2*)&q.z);
                float2 f3 = __half22float2(*(half2*)&q.w);
                selfv[0] = f0.x; selfv[1] = f0.y; selfv[2] = f1.x; selfv[3] = f1.y;
                selfv[4] = f2.x; selfv[5] = f2.y; selfv[6] = f3.x; selfv[7] = f3.y;
            } else {
                float4 p0 = h32[(size_t)n * 16 + 2 * t];
                float4 p1 = h32[(size_t)n * 16 + 2 * t + 1];
                selfv[0] = p0.x; selfv[1] = p0.y; selfv[2] = p0.z; selfv[3] = p0.w;
                selfv[4] = p1.x; selfv[5] = p1.y; selfv[6] = p1.z; selfv[7] = p1.w;
            }
            int k0 = t * 8;
#pragma unroll
            for (int c = 0; c < 8; c++)
                As[(k0 + c) * AST + nl] = di * acc[c] + d2 * selfv[c];
        }
    }
    __syncthreads();

    // ---- Phase 2: D = As^T @ W + b (+ReLU), packed f32x2 FMAs ----
    {
        int tx = tid & 15;   // n group (4 cols)
        int ty = tid >> 4;   // m group (4 rows)

        unsigned long long acc[2][4];
#pragma unroll
        for (int p = 0; p < 2; p++)
#pragma unroll
            for (int n = 0; n < 4; n++) acc[p][n] = 0ull;

#pragma unroll
        for (int k = 0; k < 64; k++) {
            float4 wv = *(const float4*)&Ws[k * 64 + tx * 4];
            unsigned long long wp0 = d_bcast2(wv.x);
            unsigned long long wp1 = d_bcast2(wv.y);
            unsigned long long wp2 = d_bcast2(wv.z);
            unsigned long long wp3 = d_bcast2(wv.w);
            unsigned long long a0 = *(const unsigned long long*)&As[k * AST + ty * 4];
            unsigned long long a1 = *(const unsigned long long*)&As[k * AST + ty * 4 + 2];
            d_fma2(acc[0][0], a0, wp0); d_fma2(acc[1][0], a1, wp0);
            d_fma2(acc[0][1], a0, wp1); d_fma2(acc[1][1], a1, wp1);
            d_fma2(acc[0][2], a0, wp2); d_fma2(acc[1][2], a1, wp2);
            d_fma2(acc[0][3], a0, wp3); d_fma2(acc[1][3], a1, wp3);
        }

        float4 bb = ((const float4*)bj)[tx];
#pragma unroll
        for (int p = 0; p < 2; p++) {
            float2 u0 = d_unpack2(acc[p][0]);
            float2 u1 = d_unpack2(acc[p][1]);
            float2 u2 = d_unpack2(acc[p][2]);
            float2 u3 = d_unpack2(acc[p][3]);
            float4 r0 = make_float4(u0.x + bb.x, u1.x + bb.y, u2.x + bb.z, u3.x + bb.w);
            float4 r1 = make_float4(u0.y + bb.x, u1.y + bb.y, u2.y + bb.z, u3.y + bb.w);
            if (relu) {
                r0.x = fmaxf(r0.x, 0.f); r0.y = fmaxf(r0.y, 0.f);
                r0.z = fmaxf(r0.z, 0.f); r0.w = fmaxf(r0.w, 0.f);
                r1.x = fmaxf(r1.x, 0.f); r1.y = fmaxf(r1.y, 0.f);
                r1.z = fmaxf(r1.z, 0.f); r1.w = fmaxf(r1.w, 0.f);
            }
            size_t row0 = (size_t)tile * 64 + ty * 4 + 2 * p;
            if (OUT16) {
                half2 p00 = __floats2half2_rn(r0.x, r0.y);
                half2 p01 = __floats2half2_rn(r0.z, r0.w);
                half2 p10 = __floats2half2_rn(r1.x, r1.y);
                half2 p11 = __floats2half2_rn(r1.z, r1.w);
                uint2 o0, o1;
                o0.x = *(unsigned int*)&p00; o0.y = *(unsigned int*)&p01;
                o1.x = *(unsigned int*)&p10; o1.y = *(unsigned int*)&p11;
                ((uint2*)hout)[((size_t)m * NN + row0) * 16 + tx] = o0;
                ((uint2*)hout)[((size_t)m * NN + row0 + 1) * 16 + tx] = o1;
            } else {
                ((float4*)hout)[((size_t)m * NN + row0) * 16 + tx] = r0;
                ((float4*)hout)[((size_t)m * NN + row0 + 1) * 16 + tx] = r1;
            }
        }
    }
}

// ---------------- launcher ----------------
extern "C" void kernel_launch(void* const* d_in, const int* in_sizes, int n_in,
                              void* d_out, int out_size) {
    const float* x  = (const float*)d_in[0];
    const int*   ei = (const int*)d_in[1];   // int32 (JAX demotes int64)
    const float* W  = (const float*)d_in[2];
    const float* b  = (const float*)d_in[3];
    float*       out = (float*)d_out;

    void* hA;
    void* hB;
    cudaGetSymbolAddress(&hA, g_hA);
    cudaGetSymbolAddress(&hB, g_hB);

    // ---- CSR build for both members ----
    k_zero_deg<<<2 * NN / 256, 256>>>();
    k_count<<<2 * NE / 256, 256>>>(ei);
    k_blocksum<<<512, 256>>>();
    k_scanb<<<2, 256>>>();
    k_rowstart<<<512, 256>>>();
    k_fill<<<2 * NE / 256, 256>>>(ei);

    // ---- 12 fused layers, both members per launch ----
    void* bufs[2] = { hA, hB };
    k_layer<false, true><<<2048, 256>>>(x, bufs[0], W, b, 0, 1);
    const void* in = bufs[0];
    for (int j = 1; j <= 10; j++) {
        void* outp = bufs[j & 1];
        k_layer<true, true><<<2048, 256>>>(in, outp, W, b, j, 1);
        in = outp;
    }
    k_layer<true, false><<<2048, 256>>>(in, out, W, b, 11, 0);
}